// round 11
// baseline (speedup 1.0000x reference)
#include <cuda_runtime.h>
#include <cuda_fp16.h>
#include <cstdint>

#define SEQ    2048
#define BATCH  64
#define IN_DIM 512
#define HID    512
#define NGATE  2048   // 4*HID, packed n = j*4 + gate (0=f,1=i,2=g,3=o)

// ---------------- device-global scratch ------------------------------------
__device__ __half g_Wxt[(size_t)NGATE * IN_DIM];          // [n][k] fp16
__device__ __half g_Wht[(size_t)NGATE * HID];             // [n][k] fp16
__device__ float  g_bias[NGATE];
__device__ __half g_Xh[(size_t)SEQ * BATCH * IN_DIM];     // fp16 X
__device__ __half g_pre[(size_t)SEQ * BATCH * NGATE];     // fp16 preacts
__device__ __half g_h[2][BATCH * HID];                    // fp16 h double buffer
__device__ unsigned g_cnt[4 * 32];                        // [bg][oct 0..3] (+pad)

// ---------------- helpers --------------------------------------------------
__device__ __forceinline__ void mma_f16(float c[4],
                                        uint32_t a0, uint32_t a1, uint32_t a2, uint32_t a3,
                                        uint32_t b0, uint32_t b1) {
    asm("mma.sync.aligned.m16n8k16.row.col.f32.f16.f16.f32 "
        "{%0,%1,%2,%3}, {%4,%5,%6,%7}, {%8,%9}, {%0,%1,%2,%3};"
        : "+f"(c[0]), "+f"(c[1]), "+f"(c[2]), "+f"(c[3])
        : "r"(a0), "r"(a1), "r"(a2), "r"(a3), "r"(b0), "r"(b1));
}

__device__ __forceinline__ void ldsm_x4(uint32_t& r0, uint32_t& r1,
                                        uint32_t& r2, uint32_t& r3, uint32_t addr) {
    asm volatile("ldmatrix.sync.aligned.m8n8.x4.shared.b16 {%0,%1,%2,%3}, [%4];"
                 : "=r"(r0), "=r"(r1), "=r"(r2), "=r"(r3) : "r"(addr));
}

__device__ __forceinline__ float tfast(float x) {
    float y;
    asm("tanh.approx.f32 %0, %1;" : "=f"(y) : "f"(x));
    return y;
}
__device__ __forceinline__ float sfast(float x) {
    return fmaf(tfast(x * 0.5f), 0.5f, 0.5f);
}

__device__ __forceinline__ uint32_t smem_u32(const void* p) {
    return (uint32_t)__cvta_generic_to_shared(p);
}
__device__ __forceinline__ void cp16(uint32_t dst, const void* src) {
    asm volatile("cp.async.cg.shared.global [%0], [%1], 16;" :: "r"(dst), "l"(src));
}
#define CP_COMMIT() asm volatile("cp.async.commit_group;")
template <int N>
__device__ __forceinline__ void cp_wait() {
    asm volatile("cp.async.wait_group %0;" :: "n"(N));
}
__device__ __forceinline__ unsigned ld_relaxed(const unsigned* p) {
    unsigned v;
    asm volatile("ld.relaxed.gpu.global.u32 %0, [%1];" : "=r"(v) : "l"(p) : "memory");
    return v;
}
#define FENCE_ACQ() asm volatile("fence.acq_rel.gpu;" ::: "memory")

// ---------------- reset (per-launch) ---------------------------------------
__global__ void reset_kernel() {
    if (threadIdx.x < 4 * 32) g_cnt[threadIdx.x] = 0u;
}

// ---------------- prep: pack weights fp16, [n][k] transposed ----------------
__global__ void prep_kernel(const float* __restrict__ Wf, const float* __restrict__ bf,
                            const float* __restrict__ Wi, const float* __restrict__ bi,
                            const float* __restrict__ Wg, const float* __restrict__ bg,
                            const float* __restrict__ Wo, const float* __restrict__ bo) {
    int idx = blockIdx.x * blockDim.x + threadIdx.x;
    if (idx < (IN_DIM + HID) * HID) {
        int k = idx >> 9;
        int j = idx & 511;
        const float* Wlist[4] = {Wf, Wi, Wg, Wo};
#pragma unroll
        for (int g = 0; g < 4; g++) {
            __half w = __float2half(Wlist[g][(size_t)k * HID + j]);
            int n = j * 4 + g;
            if (k < IN_DIM) g_Wxt[(size_t)n * IN_DIM + k] = w;
            else            g_Wht[(size_t)n * HID + (k - IN_DIM)] = w;
        }
    }
    if (idx < HID) {
        const float* blist[4] = {bf, bi, bg, bo};
#pragma unroll
        for (int g = 0; g < 4; g++) g_bias[idx * 4 + g] = blist[g][idx];
    }
}

// ---------------- convert X to fp16 ----------------------------------------
__global__ void cvtx_kernel(const float* __restrict__ X) {
    const size_t n4 = (size_t)SEQ * BATCH * IN_DIM / 4;
    const float4* src = (const float4*)X;
    uint2* dst = (uint2*)g_Xh;
    for (size_t i = blockIdx.x * blockDim.x + threadIdx.x; i < n4;
         i += (size_t)gridDim.x * blockDim.x) {
        float4 v = src[i];
        __half2 h0 = __floats2half2_rn(v.x, v.y);
        __half2 h1 = __floats2half2_rn(v.z, v.w);
        uint2 u;
        u.x = *(uint32_t*)&h0;
        u.y = *(uint32_t*)&h1;
        dst[i] = u;
    }
}

// ---------------- phase 1: pre = Xh @ Wx + bias (fp16 mma) ------------------
#define GA_H (256 * 40)
#define GB_H (128 * 40)

__device__ __forceinline__ void gemm_load_stage(__half* As, __half* Bs,
                                                int m0, int n0, int kb, int tid) {
#pragma unroll
    for (int i = 0; i < 4; i++) {
        int c = i * 256 + tid;
        int row = c >> 2, seg = c & 3;
        cp16(smem_u32(As + row * 40 + seg * 8),
             g_Xh + (size_t)(m0 + row) * IN_DIM + kb + seg * 8);
    }
#pragma unroll
    for (int i = 0; i < 2; i++) {
        int c = i * 256 + tid;
        int col = c >> 2, seg = c & 3;
        cp16(smem_u32(Bs + col * 40 + seg * 8),
             g_Wxt + (size_t)(n0 + col) * IN_DIM + kb + seg * 8);
    }
}

__global__ __launch_bounds__(256, 1) void gemm_pre_kernel() {
    extern __shared__ __half smh[];
    __half* As[3] = {smh, smh + GA_H, smh + 2 * GA_H};
    __half* Bs[3] = {smh + 3 * GA_H, smh + 3 * GA_H + GB_H, smh + 3 * GA_H + 2 * GB_H};

    const int tid  = threadIdx.x;
    const int lane = tid & 31;
    const int warp = tid >> 5;
    const int g4   = lane >> 2;
    const int q    = lane & 3;
    const int m0 = blockIdx.y * 256;
    const int n0 = blockIdx.x * 128;
    const int wm = (warp >> 1) * 64;
    const int wn = (warp & 1) * 64;

    float acc[4][8][4];
#pragma unroll
    for (int mi = 0; mi < 4; mi++)
#pragma unroll
        for (int ni = 0; ni < 8; ni++)
#pragma unroll
            for (int l = 0; l < 4; l++) acc[mi][ni][l] = 0.0f;

    gemm_load_stage(As[0], Bs[0], m0, n0, 0, tid);  CP_COMMIT();
    gemm_load_stage(As[1], Bs[1], m0, n0, 32, tid); CP_COMMIT();

    for (int kt = 0; kt < 16; kt++) {
        if (kt + 2 < 16) {
            gemm_load_stage(As[(kt + 2) % 3], Bs[(kt + 2) % 3], m0, n0, (kt + 2) * 32, tid);
            CP_COMMIT();
        }
        if (kt <= 13)      cp_wait<2>();
        else if (kt == 14) cp_wait<1>();
        else               cp_wait<0>();
        __syncthreads();

        const __half* A = As[kt % 3];
        const __half* B = Bs[kt % 3];
#pragma unroll
        for (int ks = 0; ks < 2; ks++) {
            const int k = ks * 16;
            uint32_t a[4][4], b[8][2];
#pragma unroll
            for (int mi = 0; mi < 4; mi++) {
                int mr = wm + mi * 16 + g4;
                a[mi][0] = *(const uint32_t*)&A[mr * 40 + k + 2 * q];
                a[mi][1] = *(const uint32_t*)&A[(mr + 8) * 40 + k + 2 * q];
                a[mi][2] = *(const uint32_t*)&A[mr * 40 + k + 8 + 2 * q];
                a[mi][3] = *(const uint32_t*)&A[(mr + 8) * 40 + k + 8 + 2 * q];
            }
#pragma unroll
            for (int ni = 0; ni < 8; ni++) {
                int cn = wn + ni * 8 + g4;
                b[ni][0] = *(const uint32_t*)&B[cn * 40 + k + 2 * q];
                b[ni][1] = *(const uint32_t*)&B[cn * 40 + k + 8 + 2 * q];
            }
#pragma unroll
            for (int mi = 0; mi < 4; mi++)
#pragma unroll
                for (int ni = 0; ni < 8; ni++)
                    mma_f16(acc[mi][ni], a[mi][0], a[mi][1], a[mi][2], a[mi][3],
                            b[ni][0], b[ni][1]);
        }
        __syncthreads();
    }

#pragma unroll
    for (int mi = 0; mi < 4; mi++) {
        size_t r = (size_t)(m0 + wm + mi * 16 + g4);
#pragma unroll
        for (int ni = 0; ni < 8; ni++) {
            int c = n0 + wn + ni * 8 + 2 * q;
            float2 bb = *(const float2*)&g_bias[c];
            __half2 v0 = __floats2half2_rn(acc[mi][ni][0] + bb.x, acc[mi][ni][1] + bb.y);
            __half2 v1 = __floats2half2_rn(acc[mi][ni][2] + bb.x, acc[mi][ni][3] + bb.y);
            *(__half2*)&g_pre[r * NGATE + c]       = v0;
            *(__half2*)&g_pre[(r + 8) * NGATE + c] = v1;
        }
    }
}

// ---------------- phase 2: persistent recurrence ---------------------------
// 128 CTAs = 4 bg(16 rows) x 32 jt(64 gate cols), 128 threads.
// Two-phase octet poll (chunk-0 gates on 8 producers), direct-register h
// stores, pre prefetch before mma. Empty commit on last step keeps the
// cp.async group ledger invariant (the round-10 cx bug).
#define HS_S 520   // halves
#define WS_S 520
#define PS_S 80
#define OS_S 18    // floats

#define SM_OS     0                              // 16*18*4 = 1152 (+pad 1216)
#define SM_WS     1216
#define SM_HS     (SM_WS + 64 * WS_S * 2)        // 67776
#define SM_PSM    (SM_HS + 16 * HS_S * 2)        // 84416
#define SM_TOTAL  (SM_PSM + 2 * 16 * PS_S * 2)   // 89536

__global__ __launch_bounds__(128, 1) void lstm_rec_kernel(float* __restrict__ out, int write_tail) {
    extern __shared__ char smc[];
    uint32_t sbase = smem_u32(smc);
    float*  os  = (float*)(smc + SM_OS);
    __half* Ws  = (__half*)(smc + SM_WS);
    __half* hs  = (__half*)(smc + SM_HS);
    __half* psm = (__half*)(smc + SM_PSM);

    const int tid  = threadIdx.x;
    const int lane = tid & 31;
    const int w    = tid >> 5;
    const int jt   = blockIdx.x & 31;
    const int bg   = blockIdx.x >> 5;
    const int row0 = bg * 16;
    const int nc0  = jt * 64;

    const int  g4   = lane >> 2;
    const int  q    = lane & 3;
    const bool isev = (q & 1) == 0;

    // ---- init ----
    {
        const __half* wsrc = g_Wht + (size_t)nc0 * HID;
#pragma unroll 8
        for (int i = tid; i < 64 * 64; i += 128) {
            int c = i >> 6, s = i & 63;
            *(uint4*)&Ws[c * WS_S + s * 8] = *(const uint4*)&wsrc[(size_t)c * HID + s * 8];
        }
        for (int i = tid; i < 16 * HS_S / 2; i += 128) ((uint32_t*)hs)[i] = 0u;
        // prefetch pre(0): 1 cp16/thread
        const __half* pp = g_pre + (size_t)row0 * NGATE + nc0;
        int r = tid >> 3, s = tid & 7;
        cp16(sbase + SM_PSM + (r * PS_S + s * 8) * 2, pp + (size_t)r * NGATE + s * 8);
    }
    CP_COMMIT();
    __syncthreads();

    unsigned* cnt = &g_cnt[bg * 32];            // [oct 0..3]
    unsigned* cnt_own = &g_cnt[bg * 32 + (jt >> 3)];
    float cst[2][2] = {{0.f, 0.f}, {0.f, 0.f}};

    // ldmatrix base addresses (canonical x4 mapping; validated by bit-exact rel_err)
    const uint32_t a_base = sbase + SM_HS +
        (uint32_t)(((lane & 15) * HS_S + ((lane >> 4) << 3)) * 2);
    const int bcol = (lane & 7) + ((lane >> 4) << 3);
    const int bkof = ((lane >> 3) & 1) << 3;
    const uint32_t b_base = sbase + SM_WS +
        (uint32_t)(((w * 16 + bcol) * WS_S + bkof) * 2);

    for (int t = 0; t < SEQ; t++) {
        float acc[2][4] = {{0.f, 0.f, 0.f, 0.f}, {0.f, 0.f, 0.f, 0.f}};

        auto issue_chunk = [&](int c) {
#pragma unroll
            for (int i = 0; i < 2; i++) {
                int e = i * 128 + tid;
                int r = e >> 4, s = e & 15;
                cp16(sbase + SM_HS + (r * HS_S + c * 128 + s * 8) * 2,
                     g_h[t & 1] + (size_t)(row0 + r) * HID + c * 128 + s * 8);
            }
            CP_COMMIT();
        };
        auto mma_chunk = [&](int c) {
            const int base = c * 128;
#pragma unroll
            for (int kk = 0; kk < 8; kk++) {
                const uint32_t koff = (uint32_t)(base + kk * 16) * 2;
                uint32_t a0, a1, a2, a3, b00, b01, b10, b11;
                ldsm_x4(a0, a1, a2, a3, a_base + koff);
                ldsm_x4(b00, b01, b10, b11, b_base + koff);
                mma_f16(acc[0], a0, a1, a2, a3, b00, b01);
                mma_f16(acc[1], a0, a1, a2, a3, b10, b11);
            }
        };

        if (t > 0) {
            const unsigned need = 8u * (unsigned)t;
            // phase 1: gate chunk 0 on its 8 producers only
            if (tid == 0) {
                while (ld_relaxed(&cnt[0]) < need) { }
                FENCE_ACQ();
            }
            __syncthreads();
            issue_chunk(0);
            // phase 2: remaining octets (overlaps chunk-0 flight)
            if (tid == 0) {
                for (;;) {
                    unsigned v1 = ld_relaxed(&cnt[1]);
                    unsigned v2 = ld_relaxed(&cnt[2]);
                    unsigned v3 = ld_relaxed(&cnt[3]);
                    if (v1 >= need && v2 >= need && v3 >= need) break;
                }
                FENCE_ACQ();
            }
            __syncthreads();
            issue_chunk(1); issue_chunk(2); issue_chunk(3);
        }

        // pre(t+1) prefetch — lands during mma. The commit is UNCONDITIONAL:
        // an empty group on the last step keeps every cp_wait<N> below mapped
        // to the same physical groups (omitting it corrupts step SEQ-1).
        if (t + 1 < SEQ) {
            const __half* pp = g_pre + ((size_t)(t + 1) * BATCH + row0) * NGATE + nc0;
            int r = tid >> 3, s = tid & 7;
            cp16(sbase + SM_PSM + (((t + 1) & 1) * 16 * PS_S + r * PS_S + s * 8) * 2,
                 pp + (size_t)r * NGATE + s * 8);
        }
        CP_COMMIT();

        if (t > 0) {
            cp_wait<4>(); __syncthreads(); mma_chunk(0);
            cp_wait<3>(); __syncthreads(); mma_chunk(1);
            cp_wait<2>(); __syncthreads(); mma_chunk(2);
            cp_wait<1>(); __syncthreads(); mma_chunk(3);
        } else {
            cp_wait<1>();            // pre(0) done; h == 0, skip mma
            __syncthreads();
        }

        // fused LSTM elementwise + direct h store
        {
            const __half* ps = psm + (t & 1) * 16 * PS_S;
            __half* hn = g_h[(t + 1) & 1];
#pragma unroll
            for (int ni = 0; ni < 2; ni++) {
                int nl = w * 16 + ni * 8 + 2 * q;
                float v0 = acc[ni][0] + __half2float(ps[g4 * PS_S + nl]);
                float v1 = acc[ni][1] + __half2float(ps[g4 * PS_S + nl + 1]);
                float v2 = acc[ni][2] + __half2float(ps[(g4 + 8) * PS_S + nl]);
                float v3 = acc[ni][3] + __half2float(ps[(g4 + 8) * PS_S + nl + 1]);
                float e0 = isev ? sfast(v0) : tfast(v0);
                float e1 = sfast(v1);
                float e2 = isev ? sfast(v2) : tfast(v2);
                float e3 = sfast(v3);
                float p0 = __shfl_xor_sync(0xffffffffu, e0, 1);
                float p1 = __shfl_xor_sync(0xffffffffu, e1, 1);
                float p2 = __shfl_xor_sync(0xffffffffu, e2, 1);
                float p3 = __shfl_xor_sync(0xffffffffu, e3, 1);
                float c0 = e0 * cst[ni][0] + e1 * p0;   // valid in even lanes
                float c1 = e2 * cst[ni][1] + e3 * p2;
                if (isev) { cst[ni][0] = c0; cst[ni][1] = c1; }
                float h0 = p1 * tfast(c0);              // o*tanh(c), valid even lanes
                float h1 = p3 * tfast(c1);
                float h0p = __shfl_xor_sync(0xffffffffu, h0, 2);
                float h1p = __shfl_xor_sync(0xffffffffu, h1, 2);
                if (q == 0) {                            // cols colb, colb+1
                    int colb = w * 4 + ni * 2;
                    *(float2*)&os[g4 * OS_S + colb]       = make_float2(h0, h0p);
                    *(float2*)&os[(g4 + 8) * OS_S + colb] = make_float2(h1, h1p);
                    *(__half2*)&hn[(size_t)(row0 + g4) * HID + jt * 16 + colb] =
                        __floats2half2_rn(h0, h0p);
                    *(__half2*)&hn[(size_t)(row0 + g4 + 8) * HID + jt * 16 + colb] =
                        __floats2half2_rn(h1, h1p);
                }
            }
        }
        __syncthreads();            // all h stores + os writes done CTA-wide
        if (tid == 0) {
            asm volatile("red.release.gpu.global.add.u32 [%0], %1;"
                         :: "l"(cnt_own), "r"(1u) : "memory");
        }

        // out[t] from os (off critical path)
        {
            float* op = out + ((size_t)t * BATCH + row0) * HID + jt * 16;
            int r = tid >> 3, p2i = (tid & 7) * 2;
            float2 v = *(float2*)&os[r * OS_S + p2i];
            *(float2*)&op[(size_t)r * HID + p2i] = v;
        }
    }

    if (write_tail) {
        float* hx = out + (size_t)SEQ * BATCH * HID;
        float* cx = hx + BATCH * HID;
        for (int i = tid; i < 256; i += 128) {
            int r = i >> 4, j = i & 15;
            hx[(size_t)(row0 + r) * HID + jt * 16 + j] = os[r * OS_S + j];
        }
        __syncthreads();
#pragma unroll
        for (int ni = 0; ni < 2; ni++) {
            float cs0 = cst[ni][0], cs1 = cst[ni][1];
            float cs0p = __shfl_xor_sync(0xffffffffu, cs0, 2);
            float cs1p = __shfl_xor_sync(0xffffffffu, cs1, 2);
            if (q == 0) {
                int colb = w * 4 + ni * 2;
                *(float2*)&os[g4 * OS_S + colb]       = make_float2(cs0, cs0p);
                *(float2*)&os[(g4 + 8) * OS_S + colb] = make_float2(cs1, cs1p);
            }
        }
        __syncthreads();
        for (int i = tid; i < 256; i += 128) {
            int r = i >> 4, j = i & 15;
            cx[(size_t)(row0 + r) * HID + jt * 16 + j] = os[r * OS_S + j];
        }
    }
}

// ---------------- launch ---------------------------------------------------
extern "C" void kernel_launch(void* const* d_in, const int* in_sizes, int n_in,
                              void* d_out, int out_size) {
    const float* X  = (const float*)d_in[0];
    const float* Wf = (const float*)d_in[1];
    const float* bf = (const float*)d_in[2];
    const float* Wi = (const float*)d_in[3];
    const float* bi = (const float*)d_in[4];
    const float* Wg = (const float*)d_in[5];
    const float* bg = (const float*)d_in[6];
    const float* Wo = (const float*)d_in[7];
    const float* bo = (const float*)d_in[8];
    float* out = (float*)d_out;

    reset_kernel<<<1, 128>>>();
    prep_kernel<<<((IN_DIM + HID) * HID + 255) / 256, 256>>>(Wf, bf, Wi, bi, Wg, bg, Wo, bo);
    cvtx_kernel<<<4096, 256>>>(X);

    const int smem1 = 3 * (GA_H + GB_H) * (int)sizeof(__half);
    cudaFuncSetAttribute(gemm_pre_kernel, cudaFuncAttributeMaxDynamicSharedMemorySize, smem1);
    dim3 g1(NGATE / 128, SEQ * BATCH / 256);
    gemm_pre_kernel<<<g1, 256, smem1>>>();

    cudaFuncSetAttribute(lstm_rec_kernel, cudaFuncAttributeMaxDynamicSharedMemorySize, SM_TOTAL);
    int tail = (out_size >= SEQ * BATCH * HID + 2 * BATCH * HID) ? 1 : 0;
    lstm_rec_kernel<<<128, 128, SM_TOTAL>>>(out, tail);
}

// round 12
// speedup vs baseline: 1.8213x; 1.8213x over previous
#include <cuda_runtime.h>
#include <cuda_fp16.h>
#include <cstdint>

#define SEQ    2048
#define BATCH  64
#define IN_DIM 512
#define HID    512
#define NGATE  2048   // 4*HID, packed n = j*4 + gate (0=f,1=i,2=g,3=o)

// ---------------- device-global scratch ------------------------------------
__device__ __half g_Wxt[(size_t)NGATE * IN_DIM];          // [n][k] fp16
__device__ __half g_Wht[(size_t)NGATE * HID];             // [n][k] fp16
__device__ float  g_bias[NGATE];
__device__ __half g_Xh[(size_t)SEQ * BATCH * IN_DIM];     // fp16 X
__device__ __half g_pre[(size_t)SEQ * BATCH * NGATE];     // fp16 preacts
__device__ __half g_h[2][BATCH * HID];                    // fp16 h double buffer
__device__ unsigned g_cnt[4 * 32];                        // per-bg counters (padded)

// ---------------- helpers --------------------------------------------------
__device__ __forceinline__ void mma_f16(float c[4],
                                        uint32_t a0, uint32_t a1, uint32_t a2, uint32_t a3,
                                        uint32_t b0, uint32_t b1) {
    asm("mma.sync.aligned.m16n8k16.row.col.f32.f16.f16.f32 "
        "{%0,%1,%2,%3}, {%4,%5,%6,%7}, {%8,%9}, {%0,%1,%2,%3};"
        : "+f"(c[0]), "+f"(c[1]), "+f"(c[2]), "+f"(c[3])
        : "r"(a0), "r"(a1), "r"(a2), "r"(a3), "r"(b0), "r"(b1));
}

__device__ __forceinline__ void ldsm_x4(uint32_t& r0, uint32_t& r1,
                                        uint32_t& r2, uint32_t& r3, uint32_t addr) {
    asm volatile("ldmatrix.sync.aligned.m8n8.x4.shared.b16 {%0,%1,%2,%3}, [%4];"
                 : "=r"(r0), "=r"(r1), "=r"(r2), "=r"(r3) : "r"(addr));
}

__device__ __forceinline__ float tfast(float x) {
    float y;
    asm("tanh.approx.f32 %0, %1;" : "=f"(y) : "f"(x));
    return y;
}
__device__ __forceinline__ float sfast(float x) {
    return fmaf(tfast(x * 0.5f), 0.5f, 0.5f);
}

__device__ __forceinline__ uint32_t smem_u32(const void* p) {
    return (uint32_t)__cvta_generic_to_shared(p);
}
__device__ __forceinline__ void cp16(uint32_t dst, const void* src) {
    asm volatile("cp.async.cg.shared.global [%0], [%1], 16;" :: "r"(dst), "l"(src));
}
#define CP_COMMIT() asm volatile("cp.async.commit_group;")
template <int N>
__device__ __forceinline__ void cp_wait() {
    asm volatile("cp.async.wait_group %0;" :: "n"(N));
}

// ---------------- reset (per-launch) ---------------------------------------
__global__ void reset_kernel() {
    if (threadIdx.x < 4 * 32) g_cnt[threadIdx.x] = 0u;
}

// ---------------- prep: pack weights fp16, [n][k] transposed ----------------
__global__ void prep_kernel(const float* __restrict__ Wf, const float* __restrict__ bf,
                            const float* __restrict__ Wi, const float* __restrict__ bi,
                            const float* __restrict__ Wg, const float* __restrict__ bg,
                            const float* __restrict__ Wo, const float* __restrict__ bo) {
    int idx = blockIdx.x * blockDim.x + threadIdx.x;
    if (idx < (IN_DIM + HID) * HID) {
        int k = idx >> 9;
        int j = idx & 511;
        const float* Wlist[4] = {Wf, Wi, Wg, Wo};
#pragma unroll
        for (int g = 0; g < 4; g++) {
            __half w = __float2half(Wlist[g][(size_t)k * HID + j]);
            int n = j * 4 + g;
            if (k < IN_DIM) g_Wxt[(size_t)n * IN_DIM + k] = w;
            else            g_Wht[(size_t)n * HID + (k - IN_DIM)] = w;
        }
    }
    if (idx < HID) {
        const float* blist[4] = {bf, bi, bg, bo};
#pragma unroll
        for (int g = 0; g < 4; g++) g_bias[idx * 4 + g] = blist[g][idx];
    }
}

// ---------------- convert X to fp16 ----------------------------------------
__global__ void cvtx_kernel(const float* __restrict__ X) {
    const size_t n4 = (size_t)SEQ * BATCH * IN_DIM / 4;
    const float4* src = (const float4*)X;
    uint2* dst = (uint2*)g_Xh;
    for (size_t i = blockIdx.x * blockDim.x + threadIdx.x; i < n4;
         i += (size_t)gridDim.x * blockDim.x) {
        float4 v = src[i];
        __half2 h0 = __floats2half2_rn(v.x, v.y);
        __half2 h1 = __floats2half2_rn(v.z, v.w);
        uint2 u;
        u.x = *(uint32_t*)&h0;
        u.y = *(uint32_t*)&h1;
        dst[i] = u;
    }
}

// ---------------- phase 1: pre = Xh @ Wx + bias (fp16 mma) ------------------
#define GA_H (256 * 40)
#define GB_H (128 * 40)

__device__ __forceinline__ void gemm_load_stage(__half* As, __half* Bs,
                                                int m0, int n0, int kb, int tid) {
#pragma unroll
    for (int i = 0; i < 4; i++) {
        int c = i * 256 + tid;
        int row = c >> 2, seg = c & 3;
        cp16(smem_u32(As + row * 40 + seg * 8),
             g_Xh + (size_t)(m0 + row) * IN_DIM + kb + seg * 8);
    }
#pragma unroll
    for (int i = 0; i < 2; i++) {
        int c = i * 256 + tid;
        int col = c >> 2, seg = c & 3;
        cp16(smem_u32(Bs + col * 40 + seg * 8),
             g_Wxt + (size_t)(n0 + col) * IN_DIM + kb + seg * 8);
    }
}

__global__ __launch_bounds__(256, 1) void gemm_pre_kernel() {
    extern __shared__ __half smh[];
    __half* As[3] = {smh, smh + GA_H, smh + 2 * GA_H};
    __half* Bs[3] = {smh + 3 * GA_H, smh + 3 * GA_H + GB_H, smh + 3 * GA_H + 2 * GB_H};

    const int tid  = threadIdx.x;
    const int lane = tid & 31;
    const int warp = tid >> 5;
    const int g4   = lane >> 2;
    const int q    = lane & 3;
    const int m0 = blockIdx.y * 256;
    const int n0 = blockIdx.x * 128;
    const int wm = (warp >> 1) * 64;
    const int wn = (warp & 1) * 64;

    float acc[4][8][4];
#pragma unroll
    for (int mi = 0; mi < 4; mi++)
#pragma unroll
        for (int ni = 0; ni < 8; ni++)
#pragma unroll
            for (int l = 0; l < 4; l++) acc[mi][ni][l] = 0.0f;

    gemm_load_stage(As[0], Bs[0], m0, n0, 0, tid);  CP_COMMIT();
    gemm_load_stage(As[1], Bs[1], m0, n0, 32, tid); CP_COMMIT();

    for (int kt = 0; kt < 16; kt++) {
        if (kt + 2 < 16) {
            gemm_load_stage(As[(kt + 2) % 3], Bs[(kt + 2) % 3], m0, n0, (kt + 2) * 32, tid);
            CP_COMMIT();
        }
        if (kt <= 13)      cp_wait<2>();
        else if (kt == 14) cp_wait<1>();
        else               cp_wait<0>();
        __syncthreads();

        const __half* A = As[kt % 3];
        const __half* B = Bs[kt % 3];
#pragma unroll
        for (int ks = 0; ks < 2; ks++) {
            const int k = ks * 16;
            uint32_t a[4][4], b[8][2];
#pragma unroll
            for (int mi = 0; mi < 4; mi++) {
                int mr = wm + mi * 16 + g4;
                a[mi][0] = *(const uint32_t*)&A[mr * 40 + k + 2 * q];
                a[mi][1] = *(const uint32_t*)&A[(mr + 8) * 40 + k + 2 * q];
                a[mi][2] = *(const uint32_t*)&A[mr * 40 + k + 8 + 2 * q];
                a[mi][3] = *(const uint32_t*)&A[(mr + 8) * 40 + k + 8 + 2 * q];
            }
#pragma unroll
            for (int ni = 0; ni < 8; ni++) {
                int cn = wn + ni * 8 + g4;
                b[ni][0] = *(const uint32_t*)&B[cn * 40 + k + 2 * q];
                b[ni][1] = *(const uint32_t*)&B[cn * 40 + k + 8 + 2 * q];
            }
#pragma unroll
            for (int mi = 0; mi < 4; mi++)
#pragma unroll
                for (int ni = 0; ni < 8; ni++)
                    mma_f16(acc[mi][ni], a[mi][0], a[mi][1], a[mi][2], a[mi][3],
                            b[ni][0], b[ni][1]);
        }
        __syncthreads();
    }

#pragma unroll
    for (int mi = 0; mi < 4; mi++) {
        size_t r = (size_t)(m0 + wm + mi * 16 + g4);
#pragma unroll
        for (int ni = 0; ni < 8; ni++) {
            int c = n0 + wn + ni * 8 + 2 * q;
            float2 bb = *(const float2*)&g_bias[c];
            __half2 v0 = __floats2half2_rn(acc[mi][ni][0] + bb.x, acc[mi][ni][1] + bb.y);
            __half2 v1 = __floats2half2_rn(acc[mi][ni][2] + bb.x, acc[mi][ni][3] + bb.y);
            *(__half2*)&g_pre[r * NGATE + c]       = v0;
            *(__half2*)&g_pre[(r + 8) * NGATE + c] = v1;
        }
    }
}

// ---------------- phase 2: persistent recurrence (round-7 structure) -------
// 128 CTAs = 4 bg(16 rows) x 32 jt(64 gate cols), 128 threads.
// Round-7 handoff kept verbatim (single poll, chunked cp.async + ldmatrix mma,
// bar+red.release). NEW: all B (weight) fragments hoisted into registers at
// init — Ws is static, so steady-state LDSM count and crossbar bytes halve.
#define HS_S 520   // halves
#define WS_S 520
#define PS_S 80
#define OS_S 18    // floats

#define SM_OS     0                              // 16*18*4 = 1152 (+pad 1216)
#define SM_WS     1216
#define SM_HS     (SM_WS + 64 * WS_S * 2)        // 67776
#define SM_PSM    (SM_HS + 16 * HS_S * 2)        // 84416
#define SM_TOTAL  (SM_PSM + 2 * 16 * PS_S * 2)   // 89536

__global__ __launch_bounds__(128, 1) void lstm_rec_kernel(float* __restrict__ out, int write_tail) {
    extern __shared__ char smc[];
    uint32_t sbase = smem_u32(smc);
    float*  os  = (float*)(smc + SM_OS);
    __half* Ws  = (__half*)(smc + SM_WS);
    __half* hs  = (__half*)(smc + SM_HS);
    __half* psm = (__half*)(smc + SM_PSM);

    const int tid  = threadIdx.x;
    const int lane = tid & 31;
    const int w    = tid >> 5;
    const int jt   = blockIdx.x & 31;
    const int bg   = blockIdx.x >> 5;
    const int row0 = bg * 16;
    const int nc0  = jt * 64;

    const int  g4   = lane >> 2;
    const int  q    = lane & 3;
    const bool isev = (q & 1) == 0;

    // ---- init ----
    {
        const __half* wsrc = g_Wht + (size_t)nc0 * HID;
#pragma unroll 8
        for (int i = tid; i < 64 * 64; i += 128) {
            int c = i >> 6, s = i & 63;
            *(uint4*)&Ws[c * WS_S + s * 8] = *(const uint4*)&wsrc[(size_t)c * HID + s * 8];
        }
        for (int i = tid; i < 16 * HS_S / 2; i += 128) ((uint32_t*)hs)[i] = 0u;
        // prefetch pre(0): 1 cp16/thread
        const __half* pp = g_pre + (size_t)row0 * NGATE + nc0;
        int r = tid >> 3, s = tid & 7;
        cp16(sbase + SM_PSM + (r * PS_S + s * 8) * 2, pp + (size_t)r * NGATE + s * 8);
    }
    CP_COMMIT();
    __syncthreads();

    unsigned* cnt = &g_cnt[bg * 32];
    float cst[2][2] = {{0.f, 0.f}, {0.f, 0.f}};

    // ldmatrix base addresses (canonical x4 mapping; validated bit-exact in R7)
    const uint32_t a_base = sbase + SM_HS +
        (uint32_t)(((lane & 15) * HS_S + ((lane >> 4) << 3)) * 2);
    const int bcol = (lane & 7) + ((lane >> 4) << 3);
    const int bkof = ((lane >> 3) & 1) << 3;
    const uint32_t b_base = sbase + SM_WS +
        (uint32_t)(((w * 16 + bcol) * WS_S + bkof) * 2);

    // ---- hoist ALL B fragments into registers (Ws is step-invariant) ----
    uint32_t breg[32][4];
#pragma unroll
    for (int ki = 0; ki < 32; ki++)
        ldsm_x4(breg[ki][0], breg[ki][1], breg[ki][2], breg[ki][3],
                b_base + (uint32_t)(ki * 16 * 2));

    for (int t = 0; t < SEQ; t++) {
        float acc[2][4] = {{0.f, 0.f, 0.f, 0.f}, {0.f, 0.f, 0.f, 0.f}};

        auto mma_chunk = [&](const int c) {
#pragma unroll
            for (int kk = 0; kk < 8; kk++) {
                const int ki = c * 8 + kk;
                uint32_t a0, a1, a2, a3;
                ldsm_x4(a0, a1, a2, a3, a_base + (uint32_t)(ki * 16 * 2));
                mma_f16(acc[0], a0, a1, a2, a3, breg[ki][0], breg[ki][1]);
                mma_f16(acc[1], a0, a1, a2, a3, breg[ki][2], breg[ki][3]);
            }
        };

        if (t > 0) {
            if (tid == 0) {
                unsigned v;
                const unsigned need = 32u * (unsigned)t;
                do {
                    asm volatile("ld.acquire.gpu.global.u32 %0, [%1];"
                                 : "=r"(v) : "l"(cnt) : "memory");
                } while (v < need);
            }
            __syncthreads();
            const __half* hp = g_h[t & 1];
#pragma unroll
            for (int c = 0; c < 4; c++) {
#pragma unroll
                for (int i = 0; i < 2; i++) {
                    int e = i * 128 + tid;
                    int r = e >> 4, s = e & 15;
                    cp16(sbase + SM_HS + (r * HS_S + c * 128 + s * 8) * 2,
                         hp + (size_t)(row0 + r) * HID + c * 128 + s * 8);
                }
                CP_COMMIT();
            }
            cp_wait<3>(); __syncthreads(); mma_chunk(0);
            cp_wait<2>(); __syncthreads(); mma_chunk(1);
            cp_wait<1>(); __syncthreads(); mma_chunk(2);
            cp_wait<0>(); __syncthreads(); mma_chunk(3);
        } else {
            cp_wait<0>();           // pre(0) landed; h == 0 so skip mma
            __syncthreads();
        }

        // prefetch pre(t+1) (overlaps ew + stores + next poll)
        if (t + 1 < SEQ) {
            const __half* pp = g_pre + ((size_t)(t + 1) * BATCH + row0) * NGATE + nc0;
            int r = tid >> 3, s = tid & 7;
            cp16(sbase + SM_PSM + (((t + 1) & 1) * 16 * PS_S + r * PS_S + s * 8) * 2,
                 pp + (size_t)r * NGATE + s * 8);
            CP_COMMIT();
        }

        // fused LSTM elementwise
        const __half* ps = psm + (t & 1) * 16 * PS_S;
#pragma unroll
        for (int ni = 0; ni < 2; ni++) {
            int nl = w * 16 + ni * 8 + 2 * q;
            float v0 = acc[ni][0] + __half2float(ps[g4 * PS_S + nl]);
            float v1 = acc[ni][1] + __half2float(ps[g4 * PS_S + nl + 1]);
            float v2 = acc[ni][2] + __half2float(ps[(g4 + 8) * PS_S + nl]);
            float v3 = acc[ni][3] + __half2float(ps[(g4 + 8) * PS_S + nl + 1]);
            float e0 = isev ? sfast(v0) : tfast(v0);
            float e1 = sfast(v1);
            float e2 = isev ? sfast(v2) : tfast(v2);
            float e3 = sfast(v3);
            float p0 = __shfl_xor_sync(0xffffffffu, e0, 1);
            float p1 = __shfl_xor_sync(0xffffffffu, e1, 1);
            float p2 = __shfl_xor_sync(0xffffffffu, e2, 1);
            float p3 = __shfl_xor_sync(0xffffffffu, e3, 1);
            if (isev) {
                float c0 = e0 * cst[ni][0] + e1 * p0;   // f*c + i*g
                float c1 = e2 * cst[ni][1] + e3 * p2;
                cst[ni][0] = c0;
                cst[ni][1] = c1;
                float h0 = p1 * tfast(c0);              // o*tanh(c)
                float h1 = p3 * tfast(c1);
                int jl = w * 4 + ni * 2 + (q >> 1);
                os[g4 * OS_S + jl]       = h0;
                os[(g4 + 8) * OS_S + jl] = h1;
            }
        }
        __syncthreads();

        // h store (fp16) -> bar -> release (critical path), then out (off path)
        {
            __half* hn = g_h[(t + 1) & 1];
            int r = tid >> 3, p2i = (tid & 7) * 2;
            float2 v = *(float2*)&os[r * OS_S + p2i];
            *(__half2*)&hn[(size_t)(row0 + r) * HID + jt * 16 + p2i] =
                __floats2half2_rn(v.x, v.y);
            __syncthreads();
            if (tid == 0) {
                asm volatile("red.release.gpu.global.add.u32 [%0], %1;"
                             :: "l"(cnt), "r"(1u) : "memory");
            }
            float* op = out + ((size_t)t * BATCH + row0) * HID + jt * 16;
            *(float2*)&op[(size_t)r * HID + p2i] = v;
        }
    }

    if (write_tail) {
        float* hx = out + (size_t)SEQ * BATCH * HID;
        float* cx = hx + BATCH * HID;
        for (int i = tid; i < 256; i += 128) {
            int r = i >> 4, j = i & 15;
            hx[(size_t)(row0 + r) * HID + jt * 16 + j] = os[r * OS_S + j];
        }
        __syncthreads();
#pragma unroll
        for (int ni = 0; ni < 2; ni++) {
            if (isev) {
                int jl = w * 4 + ni * 2 + (q >> 1);
                os[g4 * OS_S + jl]       = cst[ni][0];
                os[(g4 + 8) * OS_S + jl] = cst[ni][1];
            }
        }
        __syncthreads();
        for (int i = tid; i < 256; i += 128) {
            int r = i >> 4, j = i & 15;
            cx[(size_t)(row0 + r) * HID + jt * 16 + j] = os[r * OS_S + j];
        }
    }
}

// ---------------- launch ---------------------------------------------------
extern "C" void kernel_launch(void* const* d_in, const int* in_sizes, int n_in,
                              void* d_out, int out_size) {
    const float* X  = (const float*)d_in[0];
    const float* Wf = (const float*)d_in[1];
    const float* bf = (const float*)d_in[2];
    const float* Wi = (const float*)d_in[3];
    const float* bi = (const float*)d_in[4];
    const float* Wg = (const float*)d_in[5];
    const float* bg = (const float*)d_in[6];
    const float* Wo = (const float*)d_in[7];
    const float* bo = (const float*)d_in[8];
    float* out = (float*)d_out;

    reset_kernel<<<1, 128>>>();
    prep_kernel<<<((IN_DIM + HID) * HID + 255) / 256, 256>>>(Wf, bf, Wi, bi, Wg, bg, Wo, bo);
    cvtx_kernel<<<4096, 256>>>(X);

    const int smem1 = 3 * (GA_H + GB_H) * (int)sizeof(__half);
    cudaFuncSetAttribute(gemm_pre_kernel, cudaFuncAttributeMaxDynamicSharedMemorySize, smem1);
    dim3 g1(NGATE / 128, SEQ * BATCH / 256);
    gemm_pre_kernel<<<g1, 256, smem1>>>();

    cudaFuncSetAttribute(lstm_rec_kernel, cudaFuncAttributeMaxDynamicSharedMemorySize, SM_TOTAL);
    int tail = (out_size >= SEQ * BATCH * HID + 2 * BATCH * HID) ? 1 : 0;
    lstm_rec_kernel<<<128, 128, SM_TOTAL>>>(out, tail);
}

// round 14
// speedup vs baseline: 1.8391x; 1.0098x over previous
#include <cuda_runtime.h>
#include <cuda_fp16.h>
#include <cstdint>

#define SEQ    2048
#define BATCH  64
#define IN_DIM 512
#define HID    512
#define NGATE  2048   // 4*HID, packed n = j*4 + gate (0=f,1=i,2=g,3=o)

// ---------------- device-global scratch ------------------------------------
__device__ __half g_Wxt[(size_t)NGATE * IN_DIM];          // [n][k] fp16
__device__ __half g_Wht[(size_t)NGATE * HID];             // [n][k] fp16
__device__ float  g_bias[NGATE];
__device__ __half g_Xh[(size_t)SEQ * BATCH * IN_DIM];     // fp16 X
__device__ __half g_pre[(size_t)SEQ * BATCH * NGATE];     // fp16 preacts
__device__ __half g_h[2][BATCH * HID];                    // fp16 h double buffer
__device__ unsigned g_cnt[4 * 32];                        // per-bg counters (padded)

// ---------------- helpers --------------------------------------------------
__device__ __forceinline__ void mma_f16(float c[4],
                                        uint32_t a0, uint32_t a1, uint32_t a2, uint32_t a3,
                                        uint32_t b0, uint32_t b1) {
    asm("mma.sync.aligned.m16n8k16.row.col.f32.f16.f16.f32 "
        "{%0,%1,%2,%3}, {%4,%5,%6,%7}, {%8,%9}, {%0,%1,%2,%3};"
        : "+f"(c[0]), "+f"(c[1]), "+f"(c[2]), "+f"(c[3])
        : "r"(a0), "r"(a1), "r"(a2), "r"(a3), "r"(b0), "r"(b1));
}

__device__ __forceinline__ void ldsm_x4(uint32_t& r0, uint32_t& r1,
                                        uint32_t& r2, uint32_t& r3, uint32_t addr) {
    asm volatile("ldmatrix.sync.aligned.m8n8.x4.shared.b16 {%0,%1,%2,%3}, [%4];"
                 : "=r"(r0), "=r"(r1), "=r"(r2), "=r"(r3) : "r"(addr));
}

__device__ __forceinline__ float tfast(float x) {
    float y;
    asm("tanh.approx.f32 %0, %1;" : "=f"(y) : "f"(x));
    return y;
}
__device__ __forceinline__ float sfast(float x) {
    return fmaf(tfast(x * 0.5f), 0.5f, 0.5f);
}

__device__ __forceinline__ uint32_t smem_u32(const void* p) {
    return (uint32_t)__cvta_generic_to_shared(p);
}
__device__ __forceinline__ void cp16(uint32_t dst, const void* src) {
    asm volatile("cp.async.cg.shared.global [%0], [%1], 16;" :: "r"(dst), "l"(src));
}
#define CP_COMMIT() asm volatile("cp.async.commit_group;")
template <int N>
__device__ __forceinline__ void cp_wait() {
    asm volatile("cp.async.wait_group %0;" :: "n"(N));
}

// ---------------- reset (per-launch) ---------------------------------------
__global__ void reset_kernel() {
    if (threadIdx.x < 4 * 32) g_cnt[threadIdx.x] = 0u;
}

// ---------------- prep: pack weights fp16, [n][k] transposed ----------------
__global__ void prep_kernel(const float* __restrict__ Wf, const float* __restrict__ bf,
                            const float* __restrict__ Wi, const float* __restrict__ bi,
                            const float* __restrict__ Wg, const float* __restrict__ bg,
                            const float* __restrict__ Wo, const float* __restrict__ bo) {
    int idx = blockIdx.x * blockDim.x + threadIdx.x;
    if (idx < (IN_DIM + HID) * HID) {
        int k = idx >> 9;
        int j = idx & 511;
        const float* Wlist[4] = {Wf, Wi, Wg, Wo};
#pragma unroll
        for (int g = 0; g < 4; g++) {
            __half w = __float2half(Wlist[g][(size_t)k * HID + j]);
            int n = j * 4 + g;
            if (k < IN_DIM) g_Wxt[(size_t)n * IN_DIM + k] = w;
            else            g_Wht[(size_t)n * HID + (k - IN_DIM)] = w;
        }
    }
    if (idx < HID) {
        const float* blist[4] = {bf, bi, bg, bo};
#pragma unroll
        for (int g = 0; g < 4; g++) g_bias[idx * 4 + g] = blist[g][idx];
    }
}

// ---------------- convert X to fp16 ----------------------------------------
__global__ void cvtx_kernel(const float* __restrict__ X) {
    const size_t n4 = (size_t)SEQ * BATCH * IN_DIM / 4;
    const float4* src = (const float4*)X;
    uint2* dst = (uint2*)g_Xh;
    for (size_t i = blockIdx.x * blockDim.x + threadIdx.x; i < n4;
         i += (size_t)gridDim.x * blockDim.x) {
        float4 v = src[i];
        __half2 h0 = __floats2half2_rn(v.x, v.y);
        __half2 h1 = __floats2half2_rn(v.z, v.w);
        uint2 u;
        u.x = *(uint32_t*)&h0;
        u.y = *(uint32_t*)&h1;
        dst[i] = u;
    }
}

// ---------------- phase 1: pre = Xh @ Wx + bias (fp16 mma) ------------------
#define GA_H (256 * 40)
#define GB_H (128 * 40)

__device__ __forceinline__ void gemm_load_stage(__half* As, __half* Bs,
                                                int m0, int n0, int kb, int tid) {
#pragma unroll
    for (int i = 0; i < 4; i++) {
        int c = i * 256 + tid;
        int row = c >> 2, seg = c & 3;
        cp16(smem_u32(As + row * 40 + seg * 8),
             g_Xh + (size_t)(m0 + row) * IN_DIM + kb + seg * 8);
    }
#pragma unroll
    for (int i = 0; i < 2; i++) {
        int c = i * 256 + tid;
        int col = c >> 2, seg = c & 3;
        cp16(smem_u32(Bs + col * 40 + seg * 8),
             g_Wxt + (size_t)(n0 + col) * IN_DIM + kb + seg * 8);
    }
}

__global__ __launch_bounds__(256, 1) void gemm_pre_kernel() {
    extern __shared__ __half smh[];
    __half* As[3] = {smh, smh + GA_H, smh + 2 * GA_H};
    __half* Bs[3] = {smh + 3 * GA_H, smh + 3 * GA_H + GB_H, smh + 3 * GA_H + 2 * GB_H};

    const int tid  = threadIdx.x;
    const int lane = tid & 31;
    const int warp = tid >> 5;
    const int g4   = lane >> 2;
    const int q    = lane & 3;
    const int m0 = blockIdx.y * 256;
    const int n0 = blockIdx.x * 128;
    const int wm = (warp >> 1) * 64;
    const int wn = (warp & 1) * 64;

    float acc[4][8][4];
#pragma unroll
    for (int mi = 0; mi < 4; mi++)
#pragma unroll
        for (int ni = 0; ni < 8; ni++)
#pragma unroll
            for (int l = 0; l < 4; l++) acc[mi][ni][l] = 0.0f;

    gemm_load_stage(As[0], Bs[0], m0, n0, 0, tid);  CP_COMMIT();
    gemm_load_stage(As[1], Bs[1], m0, n0, 32, tid); CP_COMMIT();

    for (int kt = 0; kt < 16; kt++) {
        if (kt + 2 < 16) {
            gemm_load_stage(As[(kt + 2) % 3], Bs[(kt + 2) % 3], m0, n0, (kt + 2) * 32, tid);
            CP_COMMIT();
        }
        if (kt <= 13)      cp_wait<2>();
        else if (kt == 14) cp_wait<1>();
        else               cp_wait<0>();
        __syncthreads();

        const __half* A = As[kt % 3];
        const __half* B = Bs[kt % 3];
#pragma unroll
        for (int ks = 0; ks < 2; ks++) {
            const int k = ks * 16;
            uint32_t a[4][4], b[8][2];
#pragma unroll
            for (int mi = 0; mi < 4; mi++) {
                int mr = wm + mi * 16 + g4;
                a[mi][0] = *(const uint32_t*)&A[mr * 40 + k + 2 * q];
                a[mi][1] = *(const uint32_t*)&A[(mr + 8) * 40 + k + 2 * q];
                a[mi][2] = *(const uint32_t*)&A[mr * 40 + k + 8 + 2 * q];
                a[mi][3] = *(const uint32_t*)&A[(mr + 8) * 40 + k + 8 + 2 * q];
            }
#pragma unroll
            for (int ni = 0; ni < 8; ni++) {
                int cn = wn + ni * 8 + g4;
                b[ni][0] = *(const uint32_t*)&B[cn * 40 + k + 2 * q];
                b[ni][1] = *(const uint32_t*)&B[cn * 40 + k + 8 + 2 * q];
            }
#pragma unroll
            for (int mi = 0; mi < 4; mi++)
#pragma unroll
                for (int ni = 0; ni < 8; ni++)
                    mma_f16(acc[mi][ni], a[mi][0], a[mi][1], a[mi][2], a[mi][3],
                            b[ni][0], b[ni][1]);
        }
        __syncthreads();
    }

#pragma unroll
    for (int mi = 0; mi < 4; mi++) {
        size_t r = (size_t)(m0 + wm + mi * 16 + g4);
#pragma unroll
        for (int ni = 0; ni < 8; ni++) {
            int c = n0 + wn + ni * 8 + 2 * q;
            float2 bb = *(const float2*)&g_bias[c];
            __half2 v0 = __floats2half2_rn(acc[mi][ni][0] + bb.x, acc[mi][ni][1] + bb.y);
            __half2 v1 = __floats2half2_rn(acc[mi][ni][2] + bb.x, acc[mi][ni][3] + bb.y);
            *(__half2*)&g_pre[r * NGATE + c]       = v0;
            *(__half2*)&g_pre[(r + 8) * NGATE + c] = v1;
        }
    }
}

// ---------------- phase 2: persistent recurrence ---------------------------
// 128 CTAs = 4 bg(16 rows) x 32 jt(64 gate cols), 128 threads.
// R12 structure + B-register hoist, PLUS: direct 8B-segment hn stores from
// the ew phase (one shfl_xor(2) pairing) — removes one bar.sync and the os
// LDS readback from the inter-CTA critical path. out[] still reads os after
// the release (off path).
#define HS_S 520   // halves
#define WS_S 520
#define PS_S 80
#define OS_S 18    // floats

#define SM_OS     0                              // 16*18*4 = 1152 (+pad 1216)
#define SM_WS     1216
#define SM_HS     (SM_WS + 64 * WS_S * 2)        // 67776
#define SM_PSM    (SM_HS + 16 * HS_S * 2)        // 84416
#define SM_TOTAL  (SM_PSM + 2 * 16 * PS_S * 2)   // 89536

__global__ __launch_bounds__(128, 1) void lstm_rec_kernel(float* __restrict__ out, int write_tail) {
    extern __shared__ char smc[];
    uint32_t sbase = smem_u32(smc);
    float*  os  = (float*)(smc + SM_OS);
    __half* Ws  = (__half*)(smc + SM_WS);
    __half* hs  = (__half*)(smc + SM_HS);
    __half* psm = (__half*)(smc + SM_PSM);

    const int tid  = threadIdx.x;
    const int lane = tid & 31;
    const int w    = tid >> 5;
    const int jt   = blockIdx.x & 31;
    const int bg   = blockIdx.x >> 5;
    const int row0 = bg * 16;
    const int nc0  = jt * 64;

    const int  g4   = lane >> 2;
    const int  q    = lane & 3;
    const bool isev = (q & 1) == 0;

    // ---- init ----
    {
        const __half* wsrc = g_Wht + (size_t)nc0 * HID;
#pragma unroll 8
        for (int i = tid; i < 64 * 64; i += 128) {
            int c = i >> 6, s = i & 63;
            *(uint4*)&Ws[c * WS_S + s * 8] = *(const uint4*)&wsrc[(size_t)c * HID + s * 8];
        }
        for (int i = tid; i < 16 * HS_S / 2; i += 128) ((uint32_t*)hs)[i] = 0u;
        // prefetch pre(0): 1 cp16/thread
        const __half* pp = g_pre + (size_t)row0 * NGATE + nc0;
        int r = tid >> 3, s = tid & 7;
        cp16(sbase + SM_PSM + (r * PS_S + s * 8) * 2, pp + (size_t)r * NGATE + s * 8);
    }
    CP_COMMIT();
    __syncthreads();

    unsigned* cnt = &g_cnt[bg * 32];
    float cst[2][2] = {{0.f, 0.f}, {0.f, 0.f}};

    // ldmatrix base addresses (canonical x4 mapping; validated bit-exact in R7)
    const uint32_t a_base = sbase + SM_HS +
        (uint32_t)(((lane & 15) * HS_S + ((lane >> 4) << 3)) * 2);
    const int bcol = (lane & 7) + ((lane >> 4) << 3);
    const int bkof = ((lane >> 3) & 1) << 3;
    const uint32_t b_base = sbase + SM_WS +
        (uint32_t)(((w * 16 + bcol) * WS_S + bkof) * 2);

    // ---- hoist ALL B fragments into registers (Ws is step-invariant) ----
    uint32_t breg[32][4];
#pragma unroll
    for (int ki = 0; ki < 32; ki++)
        ldsm_x4(breg[ki][0], breg[ki][1], breg[ki][2], breg[ki][3],
                b_base + (uint32_t)(ki * 16 * 2));

    for (int t = 0; t < SEQ; t++) {
        float acc[2][4] = {{0.f, 0.f, 0.f, 0.f}, {0.f, 0.f, 0.f, 0.f}};

        auto mma_chunk = [&](const int c) {
#pragma unroll
            for (int kk = 0; kk < 8; kk++) {
                const int ki = c * 8 + kk;
                uint32_t a0, a1, a2, a3;
                ldsm_x4(a0, a1, a2, a3, a_base + (uint32_t)(ki * 16 * 2));
                mma_f16(acc[0], a0, a1, a2, a3, breg[ki][0], breg[ki][1]);
                mma_f16(acc[1], a0, a1, a2, a3, breg[ki][2], breg[ki][3]);
            }
        };

        if (t > 0) {
            if (tid == 0) {
                unsigned v;
                const unsigned need = 32u * (unsigned)t;
                do {
                    asm volatile("ld.acquire.gpu.global.u32 %0, [%1];"
                                 : "=r"(v) : "l"(cnt) : "memory");
                } while (v < need);
            }
            __syncthreads();
            const __half* hp = g_h[t & 1];
#pragma unroll
            for (int c = 0; c < 4; c++) {
#pragma unroll
                for (int i = 0; i < 2; i++) {
                    int e = i * 128 + tid;
                    int r = e >> 4, s = e & 15;
                    cp16(sbase + SM_HS + (r * HS_S + c * 128 + s * 8) * 2,
                         hp + (size_t)(row0 + r) * HID + c * 128 + s * 8);
                }
                CP_COMMIT();
            }
            cp_wait<3>(); __syncthreads(); mma_chunk(0);
            cp_wait<2>(); __syncthreads(); mma_chunk(1);
            cp_wait<1>(); __syncthreads(); mma_chunk(2);
            cp_wait<0>(); __syncthreads(); mma_chunk(3);
        } else {
            cp_wait<0>();           // pre(0) landed; h == 0 so skip mma
            __syncthreads();
        }

        // prefetch pre(t+1) (overlaps ew + stores + next poll)
        if (t + 1 < SEQ) {
            const __half* pp = g_pre + ((size_t)(t + 1) * BATCH + row0) * NGATE + nc0;
            int r = tid >> 3, s = tid & 7;
            cp16(sbase + SM_PSM + (((t + 1) & 1) * 16 * PS_S + r * PS_S + s * 8) * 2,
                 pp + (size_t)r * NGATE + s * 8);
            CP_COMMIT();
        }

        // fused LSTM elementwise + packed direct hn store (q0 lanes, 8B rows)
        {
            const __half* ps = psm + (t & 1) * 16 * PS_S;
            uint32_t hrow0[2], hrow1[2];   // per-ni packed half2 (valid in q==0)
#pragma unroll
            for (int ni = 0; ni < 2; ni++) {
                int nl = w * 16 + ni * 8 + 2 * q;
                float v0 = acc[ni][0] + __half2float(ps[g4 * PS_S + nl]);
                float v1 = acc[ni][1] + __half2float(ps[g4 * PS_S + nl + 1]);
                float v2 = acc[ni][2] + __half2float(ps[(g4 + 8) * PS_S + nl]);
                float v3 = acc[ni][3] + __half2float(ps[(g4 + 8) * PS_S + nl + 1]);
                float e0 = isev ? sfast(v0) : tfast(v0);
                float e1 = sfast(v1);
                float e2 = isev ? sfast(v2) : tfast(v2);
                float e3 = sfast(v3);
                float p0 = __shfl_xor_sync(0xffffffffu, e0, 1);
                float p1 = __shfl_xor_sync(0xffffffffu, e1, 1);
                float p2 = __shfl_xor_sync(0xffffffffu, e2, 1);
                float p3 = __shfl_xor_sync(0xffffffffu, e3, 1);
                float c0 = e0 * cst[ni][0] + e1 * p0;   // valid in even lanes
                float c1 = e2 * cst[ni][1] + e3 * p2;
                if (isev) { cst[ni][0] = c0; cst[ni][1] = c1; }
                float h0 = p1 * tfast(c0);              // valid in even lanes
                float h1 = p3 * tfast(c1);
                if (isev) {                              // os for out[] (post-release read)
                    int jl = w * 4 + ni * 2 + (q >> 1);
                    os[g4 * OS_S + jl]       = h0;
                    os[(g4 + 8) * OS_S + jl] = h1;
                }
                float h0p = __shfl_xor_sync(0xffffffffu, h0, 2);
                float h1p = __shfl_xor_sync(0xffffffffu, h1, 2);
                __half2 a2h = __floats2half2_rn(h0, h0p);   // cols jl, jl+1 (q==0)
                __half2 b2h = __floats2half2_rn(h1, h1p);
                hrow0[ni] = *(uint32_t*)&a2h;
                hrow1[ni] = *(uint32_t*)&b2h;
            }
            if (q == 0) {
                __half* hn = g_h[(t + 1) & 1];
                *(uint2*)&hn[(size_t)(row0 + g4) * HID + jt * 16 + w * 4] =
                    make_uint2(hrow0[0], hrow0[1]);
                *(uint2*)&hn[(size_t)(row0 + g4 + 8) * HID + jt * 16 + w * 4] =
                    make_uint2(hrow1[0], hrow1[1]);
            }
        }
        __syncthreads();            // hn STGs + os writes ordered CTA-wide
        if (tid == 0) {
            asm volatile("red.release.gpu.global.add.u32 [%0], %1;"
                         :: "l"(cnt), "r"(1u) : "memory");
        }

        // out[t] from os (off critical path)
        {
            float* op = out + ((size_t)t * BATCH + row0) * HID + jt * 16;
            int r = tid >> 3, p2i = (tid & 7) * 2;
            float2 v = *(float2*)&os[r * OS_S + p2i];
            *(float2*)&op[(size_t)r * HID + p2i] = v;
        }
    }

    if (write_tail) {
        float* hx = out + (size_t)SEQ * BATCH * HID;
        float* cx = hx + BATCH * HID;
        for (int i = tid; i < 256; i += 128) {
            int r = i >> 4, j = i & 15;
            hx[(size_t)(row0 + r) * HID + jt * 16 + j] = os[r * OS_S + j];
        }
        __syncthreads();
#pragma unroll
        for (int ni = 0; ni < 2; ni++) {
            if (isev) {
                int jl = w * 4 + ni * 2 + (q >> 1);
                os[g4 * OS_S + jl]       = cst[ni][0];
                os[(g4 + 8) * OS_S + jl] = cst[ni][1];
            }
        }
        __syncthreads();
        for (int i = tid; i < 256; i += 128) {
            int r = i >> 4, j = i & 15;
            cx[(size_t)(row0 + r) * HID + jt * 16 + j] = os[r * OS_S + j];
        }
    }
}

// ---------------- launch ---------------------------------------------------
extern "C" void kernel_launch(void* const* d_in, const int* in_sizes, int n_in,
                              void* d_out, int out_size) {
    const float* X  = (const float*)d_in[0];
    const float* Wf = (const float*)d_in[1];
    const float* bf = (const float*)d_in[2];
    const float* Wi = (const float*)d_in[3];
    const float* bi = (const float*)d_in[4];
    const float* Wg = (const float*)d_in[5];
    const float* bg = (const float*)d_in[6];
    const float* Wo = (const float*)d_in[7];
    const float* bo = (const float*)d_in[8];
    float* out = (float*)d_out;

    reset_kernel<<<1, 128>>>();
    prep_kernel<<<((IN_DIM + HID) * HID + 255) / 256, 256>>>(Wf, bf, Wi, bi, Wg, bg, Wo, bo);
    cvtx_kernel<<<4096, 256>>>(X);

    const int smem1 = 3 * (GA_H + GB_H) * (int)sizeof(__half);
    cudaFuncSetAttribute(gemm_pre_kernel, cudaFuncAttributeMaxDynamicSharedMemorySize, smem1);
    dim3 g1(NGATE / 128, SEQ * BATCH / 256);
    gemm_pre_kernel<<<g1, 256, smem1>>>();

    cudaFuncSetAttribute(lstm_rec_kernel, cudaFuncAttributeMaxDynamicSharedMemorySize, SM_TOTAL);
    int tail = (out_size >= SEQ * BATCH * HID + 2 * BATCH * HID) ? 1 : 0;
    lstm_rec_kernel<<<128, 128, SM_TOTAL>>>(out, tail);
}

// round 15
// speedup vs baseline: 1.8677x; 1.0155x over previous
#include <cuda_runtime.h>
#include <cuda_fp16.h>
#include <cstdint>

#define SEQ    2048
#define BATCH  64
#define IN_DIM 512
#define HID    512
#define NGATE  2048   // 4*HID, packed n = j*4 + gate (0=f,1=i,2=g,3=o)

// ---------------- device-global scratch ------------------------------------
__device__ __half g_Wxt[(size_t)NGATE * IN_DIM];          // [n][k] fp16
__device__ __half g_Wht[(size_t)NGATE * HID];             // [n][k] fp16
__device__ float  g_bias[NGATE];
__device__ __half g_Xh[(size_t)SEQ * BATCH * IN_DIM];     // fp16 X
__device__ __half g_pre[(size_t)SEQ * BATCH * NGATE];     // fp16 preacts
__device__ __half g_h[2][BATCH * HID];                    // fp16 h double buffer
__device__ unsigned g_cnt[4 * 32];                        // per-bg counters (padded)

// ---------------- helpers --------------------------------------------------
__device__ __forceinline__ void mma_f16(float c[4],
                                        uint32_t a0, uint32_t a1, uint32_t a2, uint32_t a3,
                                        uint32_t b0, uint32_t b1) {
    asm("mma.sync.aligned.m16n8k16.row.col.f32.f16.f16.f32 "
        "{%0,%1,%2,%3}, {%4,%5,%6,%7}, {%8,%9}, {%0,%1,%2,%3};"
        : "+f"(c[0]), "+f"(c[1]), "+f"(c[2]), "+f"(c[3])
        : "r"(a0), "r"(a1), "r"(a2), "r"(a3), "r"(b0), "r"(b1));
}

__device__ __forceinline__ void ldsm_x4(uint32_t& r0, uint32_t& r1,
                                        uint32_t& r2, uint32_t& r3, uint32_t addr) {
    asm volatile("ldmatrix.sync.aligned.m8n8.x4.shared.b16 {%0,%1,%2,%3}, [%4];"
                 : "=r"(r0), "=r"(r1), "=r"(r2), "=r"(r3) : "r"(addr));
}

__device__ __forceinline__ float tfast(float x) {
    float y;
    asm("tanh.approx.f32 %0, %1;" : "=f"(y) : "f"(x));
    return y;
}
__device__ __forceinline__ float sfast(float x) {
    return fmaf(tfast(x * 0.5f), 0.5f, 0.5f);
}

__device__ __forceinline__ uint32_t smem_u32(const void* p) {
    return (uint32_t)__cvta_generic_to_shared(p);
}
__device__ __forceinline__ void cp16(uint32_t dst, const void* src) {
    asm volatile("cp.async.cg.shared.global [%0], [%1], 16;" :: "r"(dst), "l"(src));
}
#define CP_COMMIT() asm volatile("cp.async.commit_group;")
template <int N>
__device__ __forceinline__ void cp_wait() {
    asm volatile("cp.async.wait_group %0;" :: "n"(N));
}

// ---------------- reset (per-launch) ---------------------------------------
__global__ void reset_kernel() {
    if (threadIdx.x < 4 * 32) g_cnt[threadIdx.x] = 0u;
}

// ---------------- prep: pack weights fp16, [n][k] transposed ----------------
__global__ void prep_kernel(const float* __restrict__ Wf, const float* __restrict__ bf,
                            const float* __restrict__ Wi, const float* __restrict__ bi,
                            const float* __restrict__ Wg, const float* __restrict__ bg,
                            const float* __restrict__ Wo, const float* __restrict__ bo) {
    int idx = blockIdx.x * blockDim.x + threadIdx.x;
    if (idx < (IN_DIM + HID) * HID) {
        int k = idx >> 9;
        int j = idx & 511;
        const float* Wlist[4] = {Wf, Wi, Wg, Wo};
#pragma unroll
        for (int g = 0; g < 4; g++) {
            __half w = __float2half(Wlist[g][(size_t)k * HID + j]);
            int n = j * 4 + g;
            if (k < IN_DIM) g_Wxt[(size_t)n * IN_DIM + k] = w;
            else            g_Wht[(size_t)n * HID + (k - IN_DIM)] = w;
        }
    }
    if (idx < HID) {
        const float* blist[4] = {bf, bi, bg, bo};
#pragma unroll
        for (int g = 0; g < 4; g++) g_bias[idx * 4 + g] = blist[g][idx];
    }
}

// ---------------- convert X to fp16 ----------------------------------------
__global__ void cvtx_kernel(const float* __restrict__ X) {
    const size_t n4 = (size_t)SEQ * BATCH * IN_DIM / 4;
    const float4* src = (const float4*)X;
    uint2* dst = (uint2*)g_Xh;
    for (size_t i = blockIdx.x * blockDim.x + threadIdx.x; i < n4;
         i += (size_t)gridDim.x * blockDim.x) {
        float4 v = src[i];
        __half2 h0 = __floats2half2_rn(v.x, v.y);
        __half2 h1 = __floats2half2_rn(v.z, v.w);
        uint2 u;
        u.x = *(uint32_t*)&h0;
        u.y = *(uint32_t*)&h1;
        dst[i] = u;
    }
}

// ---------------- phase 1: pre = Xh @ Wx + bias (fp16 mma, ldmatrix) -------
#define GA_H (256 * 40)
#define GB_H (128 * 40)

__device__ __forceinline__ void gemm_load_stage(__half* As, __half* Bs,
                                                int m0, int n0, int kb, int tid) {
#pragma unroll
    for (int i = 0; i < 4; i++) {
        int c = i * 256 + tid;
        int row = c >> 2, seg = c & 3;
        cp16(smem_u32(As + row * 40 + seg * 8),
             g_Xh + (size_t)(m0 + row) * IN_DIM + kb + seg * 8);
    }
#pragma unroll
    for (int i = 0; i < 2; i++) {
        int c = i * 256 + tid;
        int col = c >> 2, seg = c & 3;
        cp16(smem_u32(Bs + col * 40 + seg * 8),
             g_Wxt + (size_t)(n0 + col) * IN_DIM + kb + seg * 8);
    }
}

__global__ __launch_bounds__(256, 1) void gemm_pre_kernel() {
    extern __shared__ __half smh[];
    __half* As[3] = {smh, smh + GA_H, smh + 2 * GA_H};
    __half* Bs[3] = {smh + 3 * GA_H, smh + 3 * GA_H + GB_H, smh + 3 * GA_H + 2 * GB_H};

    const int tid  = threadIdx.x;
    const int lane = tid & 31;
    const int warp = tid >> 5;
    const int g4   = lane >> 2;
    const int q    = lane & 3;
    const int m0 = blockIdx.y * 256;
    const int n0 = blockIdx.x * 128;
    const int wm = (warp >> 1) * 64;
    const int wn = (warp & 1) * 64;

    // ldmatrix lane offsets (same canonical mapping validated in recurrence)
    const int arow = lane & 15;                 // A: row within 16-row tile
    const int akof = (lane >> 4) << 3;          // A: k offset 0/8
    const int bcol = (lane & 7) + ((lane >> 4) << 3);   // B: col within 16-col grp
    const int bkof = ((lane >> 3) & 1) << 3;            // B: k offset 0/8

    float acc[4][8][4];
#pragma unroll
    for (int mi = 0; mi < 4; mi++)
#pragma unroll
        for (int ni = 0; ni < 8; ni++)
#pragma unroll
            for (int l = 0; l < 4; l++) acc[mi][ni][l] = 0.0f;

    gemm_load_stage(As[0], Bs[0], m0, n0, 0, tid);  CP_COMMIT();
    gemm_load_stage(As[1], Bs[1], m0, n0, 32, tid); CP_COMMIT();

    for (int kt = 0; kt < 16; kt++) {
        if (kt + 2 < 16) {
            gemm_load_stage(As[(kt + 2) % 3], Bs[(kt + 2) % 3], m0, n0, (kt + 2) * 32, tid);
            CP_COMMIT();
        }
        if (kt <= 13)      cp_wait<2>();
        else if (kt == 14) cp_wait<1>();
        else               cp_wait<0>();
        __syncthreads();

        const uint32_t Ab = smem_u32(As[kt % 3]);
        const uint32_t Bb = smem_u32(Bs[kt % 3]);
#pragma unroll
        for (int ks = 0; ks < 2; ks++) {
            const int k = ks * 16;
            uint32_t a[4][4], b[8][2];
#pragma unroll
            for (int mi = 0; mi < 4; mi++)
                ldsm_x4(a[mi][0], a[mi][1], a[mi][2], a[mi][3],
                        Ab + (uint32_t)(((wm + mi * 16 + arow) * 40 + k + akof) * 2));
#pragma unroll
            for (int g = 0; g < 4; g++)
                ldsm_x4(b[2 * g][0], b[2 * g][1], b[2 * g + 1][0], b[2 * g + 1][1],
                        Bb + (uint32_t)(((wn + g * 16 + bcol) * 40 + k + bkof) * 2));
#pragma unroll
            for (int mi = 0; mi < 4; mi++)
#pragma unroll
                for (int ni = 0; ni < 8; ni++)
                    mma_f16(acc[mi][ni], a[mi][0], a[mi][1], a[mi][2], a[mi][3],
                            b[ni][0], b[ni][1]);
        }
        __syncthreads();
    }

#pragma unroll
    for (int mi = 0; mi < 4; mi++) {
        size_t r = (size_t)(m0 + wm + mi * 16 + g4);
#pragma unroll
        for (int ni = 0; ni < 8; ni++) {
            int c = n0 + wn + ni * 8 + 2 * q;
            float2 bb = *(const float2*)&g_bias[c];
            __half2 v0 = __floats2half2_rn(acc[mi][ni][0] + bb.x, acc[mi][ni][1] + bb.y);
            __half2 v1 = __floats2half2_rn(acc[mi][ni][2] + bb.x, acc[mi][ni][3] + bb.y);
            *(__half2*)&g_pre[r * NGATE + c]       = v0;
            *(__half2*)&g_pre[(r + 8) * NGATE + c] = v1;
        }
    }
}

// ---------------- phase 2: persistent recurrence (R14 winner, frozen) ------
#define HS_S 520   // halves
#define WS_S 520
#define PS_S 80
#define OS_S 18    // floats

#define SM_OS     0                              // 16*18*4 = 1152 (+pad 1216)
#define SM_WS     1216
#define SM_HS     (SM_WS + 64 * WS_S * 2)        // 67776
#define SM_PSM    (SM_HS + 16 * HS_S * 2)        // 84416
#define SM_TOTAL  (SM_PSM + 2 * 16 * PS_S * 2)   // 89536

__global__ __launch_bounds__(128, 1) void lstm_rec_kernel(float* __restrict__ out, int write_tail) {
    extern __shared__ char smc[];
    uint32_t sbase = smem_u32(smc);
    float*  os  = (float*)(smc + SM_OS);
    __half* Ws  = (__half*)(smc + SM_WS);
    __half* hs  = (__half*)(smc + SM_HS);
    __half* psm = (__half*)(smc + SM_PSM);

    const int tid  = threadIdx.x;
    const int lane = tid & 31;
    const int w    = tid >> 5;
    const int jt   = blockIdx.x & 31;
    const int bg   = blockIdx.x >> 5;
    const int row0 = bg * 16;
    const int nc0  = jt * 64;

    const int  g4   = lane >> 2;
    const int  q    = lane & 3;
    const bool isev = (q & 1) == 0;

    // ---- init ----
    {
        const __half* wsrc = g_Wht + (size_t)nc0 * HID;
#pragma unroll 8
        for (int i = tid; i < 64 * 64; i += 128) {
            int c = i >> 6, s = i & 63;
            *(uint4*)&Ws[c * WS_S + s * 8] = *(const uint4*)&wsrc[(size_t)c * HID + s * 8];
        }
        for (int i = tid; i < 16 * HS_S / 2; i += 128) ((uint32_t*)hs)[i] = 0u;
        // prefetch pre(0): 1 cp16/thread
        const __half* pp = g_pre + (size_t)row0 * NGATE + nc0;
        int r = tid >> 3, s = tid & 7;
        cp16(sbase + SM_PSM + (r * PS_S + s * 8) * 2, pp + (size_t)r * NGATE + s * 8);
    }
    CP_COMMIT();
    __syncthreads();

    unsigned* cnt = &g_cnt[bg * 32];
    float cst[2][2] = {{0.f, 0.f}, {0.f, 0.f}};

    // ldmatrix base addresses (canonical x4 mapping; validated bit-exact in R7)
    const uint32_t a_base = sbase + SM_HS +
        (uint32_t)(((lane & 15) * HS_S + ((lane >> 4) << 3)) * 2);
    const int bcol = (lane & 7) + ((lane >> 4) << 3);
    const int bkof = ((lane >> 3) & 1) << 3;
    const uint32_t b_base = sbase + SM_WS +
        (uint32_t)(((w * 16 + bcol) * WS_S + bkof) * 2);

    // ---- hoist ALL B fragments into registers (Ws is step-invariant) ----
    uint32_t breg[32][4];
#pragma unroll
    for (int ki = 0; ki < 32; ki++)
        ldsm_x4(breg[ki][0], breg[ki][1], breg[ki][2], breg[ki][3],
                b_base + (uint32_t)(ki * 16 * 2));

    for (int t = 0; t < SEQ; t++) {
        float acc[2][4] = {{0.f, 0.f, 0.f, 0.f}, {0.f, 0.f, 0.f, 0.f}};

        auto mma_chunk = [&](const int c) {
#pragma unroll
            for (int kk = 0; kk < 8; kk++) {
                const int ki = c * 8 + kk;
                uint32_t a0, a1, a2, a3;
                ldsm_x4(a0, a1, a2, a3, a_base + (uint32_t)(ki * 16 * 2));
                mma_f16(acc[0], a0, a1, a2, a3, breg[ki][0], breg[ki][1]);
                mma_f16(acc[1], a0, a1, a2, a3, breg[ki][2], breg[ki][3]);
            }
        };

        if (t > 0) {
            if (tid == 0) {
                unsigned v;
                const unsigned need = 32u * (unsigned)t;
                do {
                    asm volatile("ld.acquire.gpu.global.u32 %0, [%1];"
                                 : "=r"(v) : "l"(cnt) : "memory");
                } while (v < need);
            }
            __syncthreads();
            const __half* hp = g_h[t & 1];
#pragma unroll
            for (int c = 0; c < 4; c++) {
#pragma unroll
                for (int i = 0; i < 2; i++) {
                    int e = i * 128 + tid;
                    int r = e >> 4, s = e & 15;
                    cp16(sbase + SM_HS + (r * HS_S + c * 128 + s * 8) * 2,
                         hp + (size_t)(row0 + r) * HID + c * 128 + s * 8);
                }
                CP_COMMIT();
            }
            cp_wait<3>(); __syncthreads(); mma_chunk(0);
            cp_wait<2>(); __syncthreads(); mma_chunk(1);
            cp_wait<1>(); __syncthreads(); mma_chunk(2);
            cp_wait<0>(); __syncthreads(); mma_chunk(3);
        } else {
            cp_wait<0>();           // pre(0) landed; h == 0 so skip mma
            __syncthreads();
        }

        // prefetch pre(t+1) (overlaps ew + stores + next poll)
        if (t + 1 < SEQ) {
            const __half* pp = g_pre + ((size_t)(t + 1) * BATCH + row0) * NGATE + nc0;
            int r = tid >> 3, s = tid & 7;
            cp16(sbase + SM_PSM + (((t + 1) & 1) * 16 * PS_S + r * PS_S + s * 8) * 2,
                 pp + (size_t)r * NGATE + s * 8);
            CP_COMMIT();
        }

        // fused LSTM elementwise + packed direct hn store (q0 lanes, 8B rows)
        {
            const __half* ps = psm + (t & 1) * 16 * PS_S;
            uint32_t hrow0[2], hrow1[2];   // per-ni packed half2 (valid in q==0)
#pragma unroll
            for (int ni = 0; ni < 2; ni++) {
                int nl = w * 16 + ni * 8 + 2 * q;
                float v0 = acc[ni][0] + __half2float(ps[g4 * PS_S + nl]);
                float v1 = acc[ni][1] + __half2float(ps[g4 * PS_S + nl + 1]);
                float v2 = acc[ni][2] + __half2float(ps[(g4 + 8) * PS_S + nl]);
                float v3 = acc[ni][3] + __half2float(ps[(g4 + 8) * PS_S + nl + 1]);
                float e0 = isev ? sfast(v0) : tfast(v0);
                float e1 = sfast(v1);
                float e2 = isev ? sfast(v2) : tfast(v2);
                float e3 = sfast(v3);
                float p0 = __shfl_xor_sync(0xffffffffu, e0, 1);
                float p1 = __shfl_xor_sync(0xffffffffu, e1, 1);
                float p2 = __shfl_xor_sync(0xffffffffu, e2, 1);
                float p3 = __shfl_xor_sync(0xffffffffu, e3, 1);
                float c0 = e0 * cst[ni][0] + e1 * p0;   // valid in even lanes
                float c1 = e2 * cst[ni][1] + e3 * p2;
                if (isev) { cst[ni][0] = c0; cst[ni][1] = c1; }
                float h0 = p1 * tfast(c0);              // valid in even lanes
                float h1 = p3 * tfast(c1);
                if (isev) {                              // os for out[] (post-release read)
                    int jl = w * 4 + ni * 2 + (q >> 1);
                    os[g4 * OS_S + jl]       = h0;
                    os[(g4 + 8) * OS_S + jl] = h1;
                }
                float h0p = __shfl_xor_sync(0xffffffffu, h0, 2);
                float h1p = __shfl_xor_sync(0xffffffffu, h1, 2);
                __half2 a2h = __floats2half2_rn(h0, h0p);   // cols jl, jl+1 (q==0)
                __half2 b2h = __floats2half2_rn(h1, h1p);
                hrow0[ni] = *(uint32_t*)&a2h;
                hrow1[ni] = *(uint32_t*)&b2h;
            }
            if (q == 0) {
                __half* hn = g_h[(t + 1) & 1];
                *(uint2*)&hn[(size_t)(row0 + g4) * HID + jt * 16 + w * 4] =
                    make_uint2(hrow0[0], hrow0[1]);
                *(uint2*)&hn[(size_t)(row0 + g4 + 8) * HID + jt * 16 + w * 4] =
                    make_uint2(hrow1[0], hrow1[1]);
            }
        }
        __syncthreads();            // hn STGs + os writes ordered CTA-wide
        if (tid == 0) {
            asm volatile("red.release.gpu.global.add.u32 [%0], %1;"
                         :: "l"(cnt), "r"(1u) : "memory");
        }

        // out[t] from os (off critical path)
        {
            float* op = out + ((size_t)t * BATCH + row0) * HID + jt * 16;
            int r = tid >> 3, p2i = (tid & 7) * 2;
            float2 v = *(float2*)&os[r * OS_S + p2i];
            *(float2*)&op[(size_t)r * HID + p2i] = v;
        }
    }

    if (write_tail) {
        float* hx = out + (size_t)SEQ * BATCH * HID;
        float* cx = hx + BATCH * HID;
        for (int i = tid; i < 256; i += 128) {
            int r = i >> 4, j = i & 15;
            hx[(size_t)(row0 + r) * HID + jt * 16 + j] = os[r * OS_S + j];
        }
        __syncthreads();
#pragma unroll
        for (int ni = 0; ni < 2; ni++) {
            if (isev) {
                int jl = w * 4 + ni * 2 + (q >> 1);
                os[g4 * OS_S + jl]       = cst[ni][0];
                os[(g4 + 8) * OS_S + jl] = cst[ni][1];
            }
        }
        __syncthreads();
        for (int i = tid; i < 256; i += 128) {
            int r = i >> 4, j = i & 15;
            cx[(size_t)(row0 + r) * HID + jt * 16 + j] = os[r * OS_S + j];
        }
    }
}

// ---------------- launch ---------------------------------------------------
extern "C" void kernel_launch(void* const* d_in, const int* in_sizes, int n_in,
                              void* d_out, int out_size) {
    const float* X  = (const float*)d_in[0];
    const float* Wf = (const float*)d_in[1];
    const float* bf = (const float*)d_in[2];
    const float* Wi = (const float*)d_in[3];
    const float* bi = (const float*)d_in[4];
    const float* Wg = (const float*)d_in[5];
    const float* bg = (const float*)d_in[6];
    const float* Wo = (const float*)d_in[7];
    const float* bo = (const float*)d_in[8];
    float* out = (float*)d_out;

    reset_kernel<<<1, 128>>>();
    prep_kernel<<<((IN_DIM + HID) * HID + 255) / 256, 256>>>(Wf, bf, Wi, bi, Wg, bg, Wo, bo);
    cvtx_kernel<<<4096, 256>>>(X);

    const int smem1 = 3 * (GA_H + GB_H) * (int)sizeof(__half);
    cudaFuncSetAttribute(gemm_pre_kernel, cudaFuncAttributeMaxDynamicSharedMemorySize, smem1);
    dim3 g1(NGATE / 128, SEQ * BATCH / 256);
    gemm_pre_kernel<<<g1, 256, smem1>>>();

    cudaFuncSetAttribute(lstm_rec_kernel, cudaFuncAttributeMaxDynamicSharedMemorySize, SM_TOTAL);
    int tail = (out_size >= SEQ * BATCH * HID + 2 * BATCH * HID) ? 1 : 0;
    lstm_rec_kernel<<<128, 128, SM_TOTAL>>>(out, tail);
}

// round 16
// speedup vs baseline: 1.9494x; 1.0437x over previous
#include <cuda_runtime.h>
#include <cuda_fp16.h>
#include <cstdint>

#define SEQ    2048
#define BATCH  64
#define IN_DIM 512
#define HID    512
#define NGATE  2048   // 4*HID, packed n = j*4 + gate (0=f,1=i,2=g,3=o)

// ---------------- device-global scratch ------------------------------------
__device__ __half g_Wxt[(size_t)NGATE * IN_DIM];          // [n][k] fp16
__device__ __half g_Wht[(size_t)NGATE * HID];             // [n][k] fp16
__device__ float  g_bias[NGATE];
__device__ __half g_Xh[(size_t)SEQ * BATCH * IN_DIM];     // fp16 X
__device__ __half g_pre[(size_t)SEQ * BATCH * NGATE];     // fp16 preacts
__device__ __half g_h[2][BATCH * HID];                    // fp16 h double buffer
__device__ unsigned g_cnt[4 * 32];                        // per-bg counters (padded)

// ---------------- helpers --------------------------------------------------
__device__ __forceinline__ void mma_f16(float c[4],
                                        uint32_t a0, uint32_t a1, uint32_t a2, uint32_t a3,
                                        uint32_t b0, uint32_t b1) {
    asm("mma.sync.aligned.m16n8k16.row.col.f32.f16.f16.f32 "
        "{%0,%1,%2,%3}, {%4,%5,%6,%7}, {%8,%9}, {%0,%1,%2,%3};"
        : "+f"(c[0]), "+f"(c[1]), "+f"(c[2]), "+f"(c[3])
        : "r"(a0), "r"(a1), "r"(a2), "r"(a3), "r"(b0), "r"(b1));
}

__device__ __forceinline__ void ldsm_x4(uint32_t& r0, uint32_t& r1,
                                        uint32_t& r2, uint32_t& r3, uint32_t addr) {
    asm volatile("ldmatrix.sync.aligned.m8n8.x4.shared.b16 {%0,%1,%2,%3}, [%4];"
                 : "=r"(r0), "=r"(r1), "=r"(r2), "=r"(r3) : "r"(addr));
}

__device__ __forceinline__ float tfast(float x) {
    float y;
    asm("tanh.approx.f32 %0, %1;" : "=f"(y) : "f"(x));
    return y;
}
__device__ __forceinline__ float sfast(float x) {
    return fmaf(tfast(x * 0.5f), 0.5f, 0.5f);
}

__device__ __forceinline__ uint32_t smem_u32(const void* p) {
    return (uint32_t)__cvta_generic_to_shared(p);
}
__device__ __forceinline__ void cp16(uint32_t dst, const void* src) {
    asm volatile("cp.async.cg.shared.global [%0], [%1], 16;" :: "r"(dst), "l"(src));
}
#define CP_COMMIT() asm volatile("cp.async.commit_group;")
template <int N>
__device__ __forceinline__ void cp_wait() {
    asm volatile("cp.async.wait_group %0;" :: "n"(N));
}

// ---------------- reset (per-launch) ---------------------------------------
__global__ void reset_kernel() {
    if (threadIdx.x < 4 * 32) g_cnt[threadIdx.x] = 0u;
}

// ---------------- prep: pack weights fp16, [n][k] transposed ----------------
__global__ void prep_kernel(const float* __restrict__ Wf, const float* __restrict__ bf,
                            const float* __restrict__ Wi, const float* __restrict__ bi,
                            const float* __restrict__ Wg, const float* __restrict__ bg,
                            const float* __restrict__ Wo, const float* __restrict__ bo) {
    int idx = blockIdx.x * blockDim.x + threadIdx.x;
    if (idx < (IN_DIM + HID) * HID) {
        int k = idx >> 9;
        int j = idx & 511;
        const float* Wlist[4] = {Wf, Wi, Wg, Wo};
#pragma unroll
        for (int g = 0; g < 4; g++) {
            __half w = __float2half(Wlist[g][(size_t)k * HID + j]);
            int n = j * 4 + g;
            if (k < IN_DIM) g_Wxt[(size_t)n * IN_DIM + k] = w;
            else            g_Wht[(size_t)n * HID + (k - IN_DIM)] = w;
        }
    }
    if (idx < HID) {
        const float* blist[4] = {bf, bi, bg, bo};
#pragma unroll
        for (int g = 0; g < 4; g++) g_bias[idx * 4 + g] = blist[g][idx];
    }
}

// ---------------- convert X to fp16 ----------------------------------------
__global__ void cvtx_kernel(const float* __restrict__ X) {
    const size_t n4 = (size_t)SEQ * BATCH * IN_DIM / 4;
    const float4* src = (const float4*)X;
    uint2* dst = (uint2*)g_Xh;
    for (size_t i = blockIdx.x * blockDim.x + threadIdx.x; i < n4;
         i += (size_t)gridDim.x * blockDim.x) {
        float4 v = src[i];
        __half2 h0 = __floats2half2_rn(v.x, v.y);
        __half2 h1 = __floats2half2_rn(v.z, v.w);
        uint2 u;
        u.x = *(uint32_t*)&h0;
        u.y = *(uint32_t*)&h1;
        dst[i] = u;
    }
}

// ---------------- phase 1: pre = Xh @ Wx + bias -----------------------------
// CTA tile 128x128, BK=32, 3-stage cp.async, 8 warps (2m x 4n), warp 64x32.
// __launch_bounds__(256, 2): <=128 regs -> 2 CTAs/SM (4 warps/SMSP).
#define GA_H (128 * 40)   // halves per A stage
#define GB_H (128 * 40)   // halves per B stage

__device__ __forceinline__ void gemm_load_stage(__half* As, __half* Bs,
                                                int m0, int n0, int kb, int tid) {
#pragma unroll
    for (int i = 0; i < 2; i++) {
        int c = i * 256 + tid;
        int row = c >> 2, seg = c & 3;
        cp16(smem_u32(As + row * 40 + seg * 8),
             g_Xh + (size_t)(m0 + row) * IN_DIM + kb + seg * 8);
    }
#pragma unroll
    for (int i = 0; i < 2; i++) {
        int c = i * 256 + tid;
        int col = c >> 2, seg = c & 3;
        cp16(smem_u32(Bs + col * 40 + seg * 8),
             g_Wxt + (size_t)(n0 + col) * IN_DIM + kb + seg * 8);
    }
}

__global__ __launch_bounds__(256, 2) void gemm_pre_kernel() {
    extern __shared__ __half smh[];
    __half* As[3] = {smh, smh + GA_H, smh + 2 * GA_H};
    __half* Bs[3] = {smh + 3 * GA_H, smh + 3 * GA_H + GB_H, smh + 3 * GA_H + 2 * GB_H};

    const int tid  = threadIdx.x;
    const int lane = tid & 31;
    const int warp = tid >> 5;
    const int g4   = lane >> 2;
    const int q    = lane & 3;
    const int m0 = blockIdx.y * 128;
    const int n0 = blockIdx.x * 128;   // n fast -> X reuse in L2
    const int wm = (warp >> 2) * 64;   // 2 m-groups
    const int wn = (warp & 3) * 32;    // 4 n-groups

    // ldmatrix lane offsets (canonical mapping, bit-exact validated)
    const int arow = lane & 15;
    const int akof = (lane >> 4) << 3;
    const int bcol = (lane & 7) + ((lane >> 4) << 3);
    const int bkof = ((lane >> 3) & 1) << 3;

    float acc[4][4][4];
#pragma unroll
    for (int mi = 0; mi < 4; mi++)
#pragma unroll
        for (int ni = 0; ni < 4; ni++)
#pragma unroll
            for (int l = 0; l < 4; l++) acc[mi][ni][l] = 0.0f;

    gemm_load_stage(As[0], Bs[0], m0, n0, 0, tid);  CP_COMMIT();
    gemm_load_stage(As[1], Bs[1], m0, n0, 32, tid); CP_COMMIT();

    for (int kt = 0; kt < 16; kt++) {
        if (kt + 2 < 16) {
            gemm_load_stage(As[(kt + 2) % 3], Bs[(kt + 2) % 3], m0, n0, (kt + 2) * 32, tid);
            CP_COMMIT();
        }
        if (kt <= 13)      cp_wait<2>();
        else if (kt == 14) cp_wait<1>();
        else               cp_wait<0>();
        __syncthreads();

        const uint32_t Ab = smem_u32(As[kt % 3]);
        const uint32_t Bb = smem_u32(Bs[kt % 3]);
#pragma unroll
        for (int ks = 0; ks < 2; ks++) {
            const int k = ks * 16;
            uint32_t a[4][4], b[4][2];
#pragma unroll
            for (int mi = 0; mi < 4; mi++)
                ldsm_x4(a[mi][0], a[mi][1], a[mi][2], a[mi][3],
                        Ab + (uint32_t)(((wm + mi * 16 + arow) * 40 + k + akof) * 2));
#pragma unroll
            for (int g = 0; g < 2; g++)
                ldsm_x4(b[2 * g][0], b[2 * g][1], b[2 * g + 1][0], b[2 * g + 1][1],
                        Bb + (uint32_t)(((wn + g * 16 + bcol) * 40 + k + bkof) * 2));
#pragma unroll
            for (int mi = 0; mi < 4; mi++)
#pragma unroll
                for (int ni = 0; ni < 4; ni++)
                    mma_f16(acc[mi][ni], a[mi][0], a[mi][1], a[mi][2], a[mi][3],
                            b[ni][0], b[ni][1]);
        }
        __syncthreads();
    }

#pragma unroll
    for (int mi = 0; mi < 4; mi++) {
        size_t r = (size_t)(m0 + wm + mi * 16 + g4);
#pragma unroll
        for (int ni = 0; ni < 4; ni++) {
            int c = n0 + wn + ni * 8 + 2 * q;
            float2 bb = *(const float2*)&g_bias[c];
            __half2 v0 = __floats2half2_rn(acc[mi][ni][0] + bb.x, acc[mi][ni][1] + bb.y);
            __half2 v1 = __floats2half2_rn(acc[mi][ni][2] + bb.x, acc[mi][ni][3] + bb.y);
            *(__half2*)&g_pre[r * NGATE + c]       = v0;
            *(__half2*)&g_pre[(r + 8) * NGATE + c] = v1;
        }
    }
}

// ---------------- phase 2: persistent recurrence (R14 winner, frozen) ------
#define HS_S 520   // halves
#define WS_S 520
#define PS_S 80
#define OS_S 18    // floats

#define SM_OS     0                              // 16*18*4 = 1152 (+pad 1216)
#define SM_WS     1216
#define SM_HS     (SM_WS + 64 * WS_S * 2)        // 67776
#define SM_PSM    (SM_HS + 16 * HS_S * 2)        // 84416
#define SM_TOTAL  (SM_PSM + 2 * 16 * PS_S * 2)   // 89536

__global__ __launch_bounds__(128, 1) void lstm_rec_kernel(float* __restrict__ out, int write_tail) {
    extern __shared__ char smc[];
    uint32_t sbase = smem_u32(smc);
    float*  os  = (float*)(smc + SM_OS);
    __half* Ws  = (__half*)(smc + SM_WS);
    __half* hs  = (__half*)(smc + SM_HS);
    __half* psm = (__half*)(smc + SM_PSM);

    const int tid  = threadIdx.x;
    const int lane = tid & 31;
    const int w    = tid >> 5;
    const int jt   = blockIdx.x & 31;
    const int bg   = blockIdx.x >> 5;
    const int row0 = bg * 16;
    const int nc0  = jt * 64;

    const int  g4   = lane >> 2;
    const int  q    = lane & 3;
    const bool isev = (q & 1) == 0;

    // ---- init ----
    {
        const __half* wsrc = g_Wht + (size_t)nc0 * HID;
#pragma unroll 8
        for (int i = tid; i < 64 * 64; i += 128) {
            int c = i >> 6, s = i & 63;
            *(uint4*)&Ws[c * WS_S + s * 8] = *(const uint4*)&wsrc[(size_t)c * HID + s * 8];
        }
        for (int i = tid; i < 16 * HS_S / 2; i += 128) ((uint32_t*)hs)[i] = 0u;
        // prefetch pre(0): 1 cp16/thread
        const __half* pp = g_pre + (size_t)row0 * NGATE + nc0;
        int r = tid >> 3, s = tid & 7;
        cp16(sbase + SM_PSM + (r * PS_S + s * 8) * 2, pp + (size_t)r * NGATE + s * 8);
    }
    CP_COMMIT();
    __syncthreads();

    unsigned* cnt = &g_cnt[bg * 32];
    float cst[2][2] = {{0.f, 0.f}, {0.f, 0.f}};

    // ldmatrix base addresses (canonical x4 mapping; validated bit-exact in R7)
    const uint32_t a_base = sbase + SM_HS +
        (uint32_t)(((lane & 15) * HS_S + ((lane >> 4) << 3)) * 2);
    const int bcol = (lane & 7) + ((lane >> 4) << 3);
    const int bkof = ((lane >> 3) & 1) << 3;
    const uint32_t b_base = sbase + SM_WS +
        (uint32_t)(((w * 16 + bcol) * WS_S + bkof) * 2);

    // ---- hoist ALL B fragments into registers (Ws is step-invariant) ----
    uint32_t breg[32][4];
#pragma unroll
    for (int ki = 0; ki < 32; ki++)
        ldsm_x4(breg[ki][0], breg[ki][1], breg[ki][2], breg[ki][3],
                b_base + (uint32_t)(ki * 16 * 2));

    for (int t = 0; t < SEQ; t++) {
        float acc[2][4] = {{0.f, 0.f, 0.f, 0.f}, {0.f, 0.f, 0.f, 0.f}};

        auto mma_chunk = [&](const int c) {
#pragma unroll
            for (int kk = 0; kk < 8; kk++) {
                const int ki = c * 8 + kk;
                uint32_t a0, a1, a2, a3;
                ldsm_x4(a0, a1, a2, a3, a_base + (uint32_t)(ki * 16 * 2));
                mma_f16(acc[0], a0, a1, a2, a3, breg[ki][0], breg[ki][1]);
                mma_f16(acc[1], a0, a1, a2, a3, breg[ki][2], breg[ki][3]);
            }
        };

        if (t > 0) {
            if (tid == 0) {
                unsigned v;
                const unsigned need = 32u * (unsigned)t;
                do {
                    asm volatile("ld.acquire.gpu.global.u32 %0, [%1];"
                                 : "=r"(v) : "l"(cnt) : "memory");
                } while (v < need);
            }
            __syncthreads();
            const __half* hp = g_h[t & 1];
#pragma unroll
            for (int c = 0; c < 4; c++) {
#pragma unroll
                for (int i = 0; i < 2; i++) {
                    int e = i * 128 + tid;
                    int r = e >> 4, s = e & 15;
                    cp16(sbase + SM_HS + (r * HS_S + c * 128 + s * 8) * 2,
                         hp + (size_t)(row0 + r) * HID + c * 128 + s * 8);
                }
                CP_COMMIT();
            }
            cp_wait<3>(); __syncthreads(); mma_chunk(0);
            cp_wait<2>(); __syncthreads(); mma_chunk(1);
            cp_wait<1>(); __syncthreads(); mma_chunk(2);
            cp_wait<0>(); __syncthreads(); mma_chunk(3);
        } else {
            cp_wait<0>();           // pre(0) landed; h == 0 so skip mma
            __syncthreads();
        }

        // prefetch pre(t+1) (overlaps ew + stores + next poll)
        if (t + 1 < SEQ) {
            const __half* pp = g_pre + ((size_t)(t + 1) * BATCH + row0) * NGATE + nc0;
            int r = tid >> 3, s = tid & 7;
            cp16(sbase + SM_PSM + (((t + 1) & 1) * 16 * PS_S + r * PS_S + s * 8) * 2,
                 pp + (size_t)r * NGATE + s * 8);
            CP_COMMIT();
        }

        // fused LSTM elementwise + packed direct hn store (q0 lanes, 8B rows)
        {
            const __half* ps = psm + (t & 1) * 16 * PS_S;
            uint32_t hrow0[2], hrow1[2];   // per-ni packed half2 (valid in q==0)
#pragma unroll
            for (int ni = 0; ni < 2; ni++) {
                int nl = w * 16 + ni * 8 + 2 * q;
                float v0 = acc[ni][0] + __half2float(ps[g4 * PS_S + nl]);
                float v1 = acc[ni][1] + __half2float(ps[g4 * PS_S + nl + 1]);
                float v2 = acc[ni][2] + __half2float(ps[(g4 + 8) * PS_S + nl]);
                float v3 = acc[ni][3] + __half2float(ps[(g4 + 8) * PS_S + nl + 1]);
                float e0 = isev ? sfast(v0) : tfast(v0);
                float e1 = sfast(v1);
                float e2 = isev ? sfast(v2) : tfast(v2);
                float e3 = sfast(v3);
                float p0 = __shfl_xor_sync(0xffffffffu, e0, 1);
                float p1 = __shfl_xor_sync(0xffffffffu, e1, 1);
                float p2 = __shfl_xor_sync(0xffffffffu, e2, 1);
                float p3 = __shfl_xor_sync(0xffffffffu, e3, 1);
                float c0 = e0 * cst[ni][0] + e1 * p0;   // valid in even lanes
                float c1 = e2 * cst[ni][1] + e3 * p2;
                if (isev) { cst[ni][0] = c0; cst[ni][1] = c1; }
                float h0 = p1 * tfast(c0);              // valid in even lanes
                float h1 = p3 * tfast(c1);
                if (isev) {                              // os for out[] (post-release read)
                    int jl = w * 4 + ni * 2 + (q >> 1);
                    os[g4 * OS_S + jl]       = h0;
                    os[(g4 + 8) * OS_S + jl] = h1;
                }
                float h0p = __shfl_xor_sync(0xffffffffu, h0, 2);
                float h1p = __shfl_xor_sync(0xffffffffu, h1, 2);
                __half2 a2h = __floats2half2_rn(h0, h0p);   // cols jl, jl+1 (q==0)
                __half2 b2h = __floats2half2_rn(h1, h1p);
                hrow0[ni] = *(uint32_t*)&a2h;
                hrow1[ni] = *(uint32_t*)&b2h;
            }
            if (q == 0) {
                __half* hn = g_h[(t + 1) & 1];
                *(uint2*)&hn[(size_t)(row0 + g4) * HID + jt * 16 + w * 4] =
                    make_uint2(hrow0[0], hrow0[1]);
                *(uint2*)&hn[(size_t)(row0 + g4 + 8) * HID + jt * 16 + w * 4] =
                    make_uint2(hrow1[0], hrow1[1]);
            }
        }
        __syncthreads();            // hn STGs + os writes ordered CTA-wide
        if (tid == 0) {
            asm volatile("red.release.gpu.global.add.u32 [%0], %1;"
                         :: "l"(cnt), "r"(1u) : "memory");
        }

        // out[t] from os (off critical path)
        {
            float* op = out + ((size_t)t * BATCH + row0) * HID + jt * 16;
            int r = tid >> 3, p2i = (tid & 7) * 2;
            float2 v = *(float2*)&os[r * OS_S + p2i];
            *(float2*)&op[(size_t)r * HID + p2i] = v;
        }
    }

    if (write_tail) {
        float* hx = out + (size_t)SEQ * BATCH * HID;
        float* cx = hx + BATCH * HID;
        for (int i = tid; i < 256; i += 128) {
            int r = i >> 4, j = i & 15;
            hx[(size_t)(row0 + r) * HID + jt * 16 + j] = os[r * OS_S + j];
        }
        __syncthreads();
#pragma unroll
        for (int ni = 0; ni < 2; ni++) {
            if (isev) {
                int jl = w * 4 + ni * 2 + (q >> 1);
                os[g4 * OS_S + jl]       = cst[ni][0];
                os[(g4 + 8) * OS_S + jl] = cst[ni][1];
            }
        }
        __syncthreads();
        for (int i = tid; i < 256; i += 128) {
            int r = i >> 4, j = i & 15;
            cx[(size_t)(row0 + r) * HID + jt * 16 + j] = os[r * OS_S + j];
        }
    }
}

// ---------------- launch ---------------------------------------------------
extern "C" void kernel_launch(void* const* d_in, const int* in_sizes, int n_in,
                              void* d_out, int out_size) {
    const float* X  = (const float*)d_in[0];
    const float* Wf = (const float*)d_in[1];
    const float* bf = (const float*)d_in[2];
    const float* Wi = (const float*)d_in[3];
    const float* bi = (const float*)d_in[4];
    const float* Wg = (const float*)d_in[5];
    const float* bg = (const float*)d_in[6];
    const float* Wo = (const float*)d_in[7];
    const float* bo = (const float*)d_in[8];
    float* out = (float*)d_out;

    reset_kernel<<<1, 128>>>();
    prep_kernel<<<((IN_DIM + HID) * HID + 255) / 256, 256>>>(Wf, bf, Wi, bi, Wg, bg, Wo, bo);
    cvtx_kernel<<<4096, 256>>>(X);

    const int smem1 = 3 * (GA_H + GB_H) * (int)sizeof(__half);
    cudaFuncSetAttribute(gemm_pre_kernel, cudaFuncAttributeMaxDynamicSharedMemorySize, smem1);
    dim3 g1(NGATE / 128, SEQ * BATCH / 128);
    gemm_pre_kernel<<<g1, 256, smem1>>>();

    cudaFuncSetAttribute(lstm_rec_kernel, cudaFuncAttributeMaxDynamicSharedMemorySize, SM_TOTAL);
    int tail = (out_size >= SEQ * BATCH * HID + 2 * BATCH * HID) ? 1 : 0;
    lstm_rec_kernel<<<128, 128, SM_TOTAL>>>(out, tail);
}